// round 2
// baseline (speedup 1.0000x reference)
#include <cuda_runtime.h>

// ---------------------------------------------------------------------------
// AdderNet 6-layer stack: adder_conv -> BN(train stats) -> ReLU6, fused where
// possible. Conv kernel is a GEMM-shaped smem-tiled kernel computing
//   pre[m, co] = -sum_k |act(P[m,k]) - W[co,k]|
// with the previous layer's BN+ReLU6 applied on the fly during P-tile load.
// Per-layer channel statistics are reduced in double precision, folded into
// (scale, shift) consumed by the next conv (or the final apply kernel).
// ---------------------------------------------------------------------------

#define BM 64
#define BN 64
#define BK 16
#define TM 4
#define TN 8
#define CONV_THREADS 128

// Ping-pong scratch (device globals; no runtime allocation allowed).
__device__ float g_bufA[16 * 256 * 38 * 38];   // 5,914,624 floats (23.7 MB)
__device__ float g_bufB[16 * 512 * 19 * 19];   // 2,957,312 floats (11.8 MB)
__device__ float g_scale[6][512];
__device__ float g_shift[6][512];

__global__ __launch_bounds__(CONV_THREADS)
void adder_conv_kernel(const float* __restrict__ x,
                       const float* __restrict__ w,
                       float* __restrict__ out,
                       const float* __restrict__ in_scale,
                       const float* __restrict__ in_shift,
                       int do_act,
                       int N, int Cin, int H, int W,
                       int Cout, int KH, int KW,
                       int stride, int pad, int Ho, int Wo)
{
    __shared__ float sP[BK][BM];
    __shared__ float sW[BK][BN + 4];   // +4 floats keeps 16B alignment, kills STS conflicts

    const int M    = N * Ho * Wo;
    const int K    = Cin * KH * KW;
    const int HoWo = Ho * Wo;
    const int KHW  = KH * KW;

    const int tid = threadIdx.x;
    const int m0  = blockIdx.x * BM;
    const int n0  = blockIdx.y * BN;

    const int tx  = tid & 15;          // 16 groups along M
    const int ty  = tid >> 4;          // 8 groups along N
    const int tm0 = tx * TM;
    const int tn0 = ty * TN;

    float acc[TM][TN];
#pragma unroll
    for (int i = 0; i < TM; i++)
#pragma unroll
        for (int j = 0; j < TN; j++) acc[i][j] = 0.f;

    for (int k0 = 0; k0 < K; k0 += BK) {
        // ---- load P tile (BK x BM), activation applied on the fly ----
#pragma unroll
        for (int r = 0; r < (BK * BM) / CONV_THREADS; r++) {
            int idx = r * CONV_THREADS + tid;
            int lm  = idx & (BM - 1);
            int lk  = idx >> 6;        // idx / BM
            int m   = m0 + lm;
            int k   = k0 + lk;
            float v = 0.f;
            if (m < M) {
                int c, ky, kx;
                if (KHW == 1) { c = k; ky = 0; kx = 0; }
                else {
                    c = k / KHW;
                    int rem = k - c * KHW;
                    ky = rem / KW;
                    kx = rem - ky * KW;
                }
                int n  = m / HoWo;
                int s  = m - n * HoWo;
                int oy = s / Wo;
                int ox = s - oy * Wo;
                int iy = oy * stride - pad + ky;
                int ix = ox * stride - pad + kx;
                if (iy >= 0 && iy < H && ix >= 0 && ix < W) {
                    v = x[((n * Cin + c) * H + iy) * W + ix];
                    if (do_act) {
                        v = fminf(fmaxf(fmaf(v, in_scale[c], in_shift[c]), 0.f), 6.f);
                    }
                }
            }
            sP[lk][lm] = v;
        }
        // ---- load W tile (BK x BN), transposed store ----
#pragma unroll
        for (int r = 0; r < (BK * BN) / CONV_THREADS; r++) {
            int idx = r * CONV_THREADS + tid;
            int lk  = idx & (BK - 1);
            int lco = idx >> 4;        // idx / BK
            sW[lk][lco] = w[(n0 + lco) * K + (k0 + lk)];
        }
        __syncthreads();

        // ---- compute ----
#pragma unroll
        for (int kk = 0; kk < BK; kk++) {
            float4 p4  = *reinterpret_cast<const float4*>(&sP[kk][tm0]);
            float4 w4a = *reinterpret_cast<const float4*>(&sW[kk][tn0]);
            float4 w4b = *reinterpret_cast<const float4*>(&sW[kk][tn0 + 4]);
            float pv[TM] = {p4.x, p4.y, p4.z, p4.w};
            float wv[TN] = {w4a.x, w4a.y, w4a.z, w4a.w,
                            w4b.x, w4b.y, w4b.z, w4b.w};
#pragma unroll
            for (int i = 0; i < TM; i++)
#pragma unroll
                for (int j = 0; j < TN; j++)
                    acc[i][j] += fabsf(pv[i] - wv[j]);
        }
        __syncthreads();
    }

    // ---- writeback: out is NCHW, value = -acc ----
#pragma unroll
    for (int i = 0; i < TM; i++) {
        int m = m0 + tm0 + i;
        if (m < M) {
            int n = m / HoWo;
            int s = m - n * HoWo;
            float* op = out + (size_t)(n * Cout + n0 + tn0) * HoWo + s;
#pragma unroll
            for (int j = 0; j < TN; j++) {
                op[(size_t)j * HoWo] = -acc[i][j];
            }
        }
    }
}

// Per-channel training-mode BN stats -> folded (scale, shift).
__global__ void bn_stats_kernel(const float* __restrict__ pre,
                                const float* __restrict__ gamma,
                                const float* __restrict__ beta,
                                float* __restrict__ scale,
                                float* __restrict__ shift,
                                int N, int Cout, int HoWo)
{
    const int c   = blockIdx.x;
    const int tid = threadIdx.x;
    const int cnt = N * HoWo;

    double s = 0.0, sq = 0.0;
    for (int i = tid; i < cnt; i += blockDim.x) {
        int n  = i / HoWo;
        int sp = i - n * HoWo;
        float v = pre[(size_t)(n * Cout + c) * HoWo + sp];
        s  += (double)v;
        sq += (double)v * (double)v;
    }
    __shared__ double ss[256];
    __shared__ double ssq[256];
    ss[tid]  = s;
    ssq[tid] = sq;
    __syncthreads();
    for (int o = 128; o > 0; o >>= 1) {
        if (tid < o) { ss[tid] += ss[tid + o]; ssq[tid] += ssq[tid + o]; }
        __syncthreads();
    }
    if (tid == 0) {
        double mean = ss[0] / cnt;
        double var  = ssq[0] / cnt - mean * mean;
        float rstd  = (float)(1.0 / sqrt(var + 1e-5));
        float sc    = gamma[c] * rstd;
        scale[c]    = sc;
        shift[c]    = beta[c] - (float)mean * sc;
    }
}

// Final layer: apply BN + ReLU6 to d_out.
__global__ void apply_bn_relu6(const float* __restrict__ pre,
                               float* __restrict__ out,
                               const float* __restrict__ scale,
                               const float* __restrict__ shift,
                               int total, int HoWo, int Cout)
{
    int i = blockIdx.x * blockDim.x + threadIdx.x;
    if (i < total) {
        int c = (i / HoWo) % Cout;
        out[i] = fminf(fmaxf(fmaf(pre[i], scale[c], shift[c]), 0.f), 6.f);
    }
}

static void launch_conv(const float* x, const float* w, float* out,
                        const float* in_scale, const float* in_shift, int do_act,
                        int N, int Cin, int H, int W,
                        int Cout, int KH, int KW, int stride, int pad)
{
    int Ho = (H + 2 * pad - KH) / stride + 1;
    int Wo = (W + 2 * pad - KW) / stride + 1;
    int M  = N * Ho * Wo;
    dim3 grid((M + BM - 1) / BM, Cout / BN);
    adder_conv_kernel<<<grid, CONV_THREADS>>>(x, w, out, in_scale, in_shift, do_act,
                                              N, Cin, H, W, Cout, KH, KW,
                                              stride, pad, Ho, Wo);
}

extern "C" void kernel_launch(void* const* d_in, const int* in_sizes, int n_in,
                              void* d_out, int out_size)
{
    (void)in_sizes; (void)n_in; (void)out_size;
    const float* x = (const float*)d_in[0];
    const float* W[6];
    const float* G[6];
    const float* B[6];
    for (int i = 0; i < 6; i++) {
        W[i] = (const float*)d_in[1 + 3 * i];
        G[i] = (const float*)d_in[2 + 3 * i];
        B[i] = (const float*)d_in[3 + 3 * i];
    }

    float *bufA, *bufB, *scl, *shf;
    cudaGetSymbolAddress((void**)&bufA, g_bufA);
    cudaGetSymbolAddress((void**)&bufB, g_bufB);
    cudaGetSymbolAddress((void**)&scl,  g_scale);
    cudaGetSymbolAddress((void**)&shf,  g_shift);
    float* SC[6]; float* SH[6];
    for (int i = 0; i < 6; i++) { SC[i] = scl + i * 512; SH[i] = shf + i * 512; }

    const int Nb = 16;

    // L1: 1x1 512->256, 38x38, no input activation
    launch_conv(x, W[0], bufA, nullptr, nullptr, 0, Nb, 512, 38, 38, 256, 1, 1, 1, 0);
    bn_stats_kernel<<<256, 256>>>(bufA, G[0], B[0], SC[0], SH[0], Nb, 256, 38 * 38);

    // L2: 3x3 256->512, stride 2 pad 1 -> 19x19
    launch_conv(bufA, W[1], bufB, SC[0], SH[0], 1, Nb, 256, 38, 38, 512, 3, 3, 2, 1);
    bn_stats_kernel<<<512, 256>>>(bufB, G[1], B[1], SC[1], SH[1], Nb, 512, 19 * 19);

    // L3: 1x1 512->128, 19x19
    launch_conv(bufB, W[2], bufA, SC[1], SH[1], 1, Nb, 512, 19, 19, 128, 1, 1, 1, 0);
    bn_stats_kernel<<<128, 256>>>(bufA, G[2], B[2], SC[2], SH[2], Nb, 128, 19 * 19);

    // L4: 3x3 128->256, stride 2 pad 1 -> 10x10
    launch_conv(bufA, W[3], bufB, SC[2], SH[2], 1, Nb, 128, 19, 19, 256, 3, 3, 2, 1);
    bn_stats_kernel<<<256, 256>>>(bufB, G[3], B[3], SC[3], SH[3], Nb, 256, 10 * 10);

    // L5: 1x1 256->128, 10x10
    launch_conv(bufB, W[4], bufA, SC[3], SH[3], 1, Nb, 256, 10, 10, 128, 1, 1, 1, 0);
    bn_stats_kernel<<<128, 256>>>(bufA, G[4], B[4], SC[4], SH[4], Nb, 128, 10 * 10);

    // L6: 3x3 128->256, stride 2 pad 0 -> 4x4
    launch_conv(bufA, W[5], bufB, SC[4], SH[4], 1, Nb, 128, 10, 10, 256, 3, 3, 2, 0);
    bn_stats_kernel<<<256, 256>>>(bufB, G[5], B[5], SC[5], SH[5], Nb, 256, 4 * 4);

    // Final BN + ReLU6 -> d_out  [16, 256, 4, 4]
    int total = Nb * 256 * 4 * 4;
    apply_bn_relu6<<<(total + 255) / 256, 256>>>(bufB, (float*)d_out, SC[5], SH[5],
                                                 total, 4 * 4, 256);
}

// round 3
// speedup vs baseline: 1.0902x; 1.0902x over previous
#include <cuda_runtime.h>

typedef unsigned long long u64;
#define ABS2_MASK 0x7FFFFFFF7FFFFFFFull

// Packed fp32x2 add (sm_103a). One fma-pipe instruction, 2 FP32 adds per lane.
__device__ __forceinline__ u64 addx2(u64 a, u64 b) {
    u64 d;
    asm("add.rn.f32x2 %0, %1, %2;" : "=l"(d) : "l"(a), "l"(b));
    return d;
}

// ---------------- scratch (device globals; no runtime allocation) ----------
__device__ float  g_bufA[16 * 256 * 38 * 38];   // 23.7 MB ping
__device__ float  g_bufB[16 * 512 * 19 * 19];   // 11.8 MB pong
__device__ double g_sum[6][512];
__device__ double g_sumsq[6][512];
__device__ float  g_scale[6][512];
__device__ float  g_shift[6][512];

__global__ void zero_stats_kernel() {
    int i = blockIdx.x * blockDim.x + threadIdx.x;
    if (i < 6 * 512) {
        (&g_sum[0][0])[i]   = 0.0;
        (&g_sumsq[0][0])[i] = 0.0;
    }
}

// ---------------------------------------------------------------------------
// Adder conv, GEMM-shaped:  pre[m, co] = -sum_k |act(P[m,k]) - W[co,k]|
// - previous layer's BN+ReLU6 folded into the P-tile load
// - packed f32x2 math: 2 M-rows per 64-bit lane; weights stored negated+dup
// - per-channel sum/sumsq reduced in-block and atomically added (double)
// ---------------------------------------------------------------------------
template<int BM, int BN, int TM, int TN>
__global__ __launch_bounds__(128)
void adder_conv(const float* __restrict__ x, const float* __restrict__ w,
                float* __restrict__ out,
                const float* __restrict__ in_scale,
                const float* __restrict__ in_shift,
                int do_act,
                double* __restrict__ sum_g, double* __restrict__ sumsq_g,
                int N, int Cin, int H, int W,
                int Cout, int KH, int KW,
                int stride, int pad, int Ho, int Wo)
{
    constexpr int BK   = 16;
    constexpr int NT   = 128;
    constexpr int WPAD = 8;                 // de-conflict STS into sW rows
    __shared__ float sP[BK][BM];
    __shared__ float sW[BK][2 * BN + WPAD]; // negated, duplicated weights

    const int M    = N * Ho * Wo;
    const int K    = Cin * KH * KW;
    const int HoWo = Ho * Wo;
    const int KHW  = KH * KW;

    const int tid = threadIdx.x;
    const int m0  = blockIdx.x * BM;
    const int n0  = blockIdx.y * BN;
    const int txm = tid & 7;        // 8 groups along M
    const int ty  = tid >> 3;       // 16 groups along N
    const int tm0 = txm * TM;
    const int tn0 = ty * TN;

    u64 acc[TM / 2][TN];
#pragma unroll
    for (int i = 0; i < TM / 2; i++)
#pragma unroll
        for (int j = 0; j < TN; j++) acc[i][j] = 0ull;

    for (int k0 = 0; k0 < K; k0 += BK) {
        // ---- P tile (BK x BM), activation folded in; OOB patch -> 0 ----
#pragma unroll
        for (int r = 0; r < (BK * BM) / NT; r++) {
            int idx = r * NT + tid;
            int lm  = idx & (BM - 1);
            int lk  = idx / BM;
            int m   = m0 + lm;
            int k   = k0 + lk;
            float v = 0.f;
            if (m < M) {
                int c, ky, kx;
                if (KHW == 1) { c = k; ky = 0; kx = 0; }
                else {
                    c = k / KHW;
                    int rem = k - c * KHW;
                    ky = rem / KW;
                    kx = rem - ky * KW;
                }
                int n  = m / HoWo;
                int s  = m - n * HoWo;
                int oy = s / Wo;
                int ox = s - oy * Wo;
                int iy = oy * stride - pad + ky;
                int ix = ox * stride - pad + kx;
                if (iy >= 0 && iy < H && ix >= 0 && ix < W) {
                    v = x[((n * Cin + c) * H + iy) * W + ix];
                    if (do_act)
                        v = fminf(fmaxf(fmaf(v, in_scale[c], in_shift[c]), 0.f), 6.f);
                }
            }
            sP[lk][lm] = v;
        }
        // ---- W tile: load coalesced, store negated + duplicated ----
#pragma unroll
        for (int r = 0; r < (BK * BN) / NT; r++) {
            int idx  = r * NT + tid;
            int lk   = idx & (BK - 1);
            int lco  = idx >> 4;
            float wv = -w[(n0 + lco) * K + (k0 + lk)];
            *reinterpret_cast<float2*>(&sW[lk][2 * lco]) = make_float2(wv, wv);
        }
        __syncthreads();

        // ---- compute: packed sub(add-neg) / packed-abs(LOP3) / packed add ----
#pragma unroll
        for (int kk = 0; kk < BK; kk++) {
            u64 p2[TM / 2];
#pragma unroll
            for (int i = 0; i < TM / 4; i++) {
                ulonglong2 t = *reinterpret_cast<const ulonglong2*>(&sP[kk][tm0 + 4 * i]);
                p2[2 * i]     = t.x;
                p2[2 * i + 1] = t.y;
            }
            u64 w2[TN];
#pragma unroll
            for (int j = 0; j < TN / 2; j++) {
                ulonglong2 t = *reinterpret_cast<const ulonglong2*>(&sW[kk][2 * tn0 + 4 * j]);
                w2[2 * j]     = t.x;
                w2[2 * j + 1] = t.y;
            }
#pragma unroll
            for (int i = 0; i < TM / 2; i++)
#pragma unroll
                for (int j = 0; j < TN; j++) {
                    u64 d = addx2(p2[i], w2[j]) & ABS2_MASK;
                    acc[i][j] = addx2(acc[i][j], d);
                }
        }
        __syncthreads();
    }

    // ---- writeback (-acc) + per-channel stats ----
    float s_sum[TN], s_sq[TN];
#pragma unroll
    for (int j = 0; j < TN; j++) { s_sum[j] = 0.f; s_sq[j] = 0.f; }

#pragma unroll
    for (int i = 0; i < TM / 2; i++) {
        int mA = m0 + tm0 + 2 * i;
        int mB = mA + 1;
        bool okA = mA < M, okB = mB < M;
        int nA = 0, sA = 0, nB = 0, sB = 0;
        if (okA) { nA = mA / HoWo; sA = mA - nA * HoWo; }
        if (okB) { nB = mB / HoWo; sB = mB - nB * HoWo; }
#pragma unroll
        for (int j = 0; j < TN; j++) {
            float lo = __uint_as_float((unsigned int)(acc[i][j] & 0xFFFFFFFFull));
            float hi = __uint_as_float((unsigned int)(acc[i][j] >> 32));
            float vA = -lo, vB = -hi;
            int c = n0 + tn0 + j;
            if (okA) {
                out[(size_t)(nA * Cout + c) * HoWo + sA] = vA;
                s_sum[j] += vA; s_sq[j] += vA * vA;
            }
            if (okB) {
                out[(size_t)(nB * Cout + c) * HoWo + sB] = vB;
                s_sum[j] += vB; s_sq[j] += vB * vB;
            }
        }
    }
    // reduce over the 8 M-thread-groups (lane bits 0..2), then atomics
#pragma unroll
    for (int j = 0; j < TN; j++) {
        float a = s_sum[j], b = s_sq[j];
#pragma unroll
        for (int o = 1; o < 8; o <<= 1) {
            a += __shfl_xor_sync(0xffffffffu, a, o);
            b += __shfl_xor_sync(0xffffffffu, b, o);
        }
        if (txm == 0) {
            int c = n0 + tn0 + j;
            atomicAdd(&sum_g[c],   (double)a);
            atomicAdd(&sumsq_g[c], (double)b);
        }
    }
}

__global__ void finalize_bn(const double* __restrict__ sum_g,
                            const double* __restrict__ sumsq_g,
                            const float* __restrict__ gamma,
                            const float* __restrict__ beta,
                            float* __restrict__ scale,
                            float* __restrict__ shift,
                            int Cout, int cnt)
{
    int c = blockIdx.x * blockDim.x + threadIdx.x;
    if (c < Cout) {
        double mean = sum_g[c] / cnt;
        double var  = sumsq_g[c] / cnt - mean * mean;
        float rstd  = (float)(1.0 / sqrt(var + 1e-5));
        float sc    = gamma[c] * rstd;
        scale[c]    = sc;
        shift[c]    = beta[c] - (float)mean * sc;
    }
}

__global__ void apply_bn_relu6(const float* __restrict__ pre,
                               float* __restrict__ out,
                               const float* __restrict__ scale,
                               const float* __restrict__ shift,
                               int total, int HoWo, int Cout)
{
    int i = blockIdx.x * blockDim.x + threadIdx.x;
    if (i < total) {
        int c = (i / HoWo) % Cout;
        out[i] = fminf(fmaxf(fmaf(pre[i], scale[c], shift[c]), 0.f), 6.f);
    }
}

template<int BM, int BN, int TM, int TN>
static void run_conv(const float* x, const float* w, float* out,
                     const float* sc, const float* sh, int act,
                     double* sum_g, double* sumsq_g,
                     int N, int Cin, int H, int W,
                     int Cout, int KH, int KW, int stride, int pad)
{
    int Ho = (H + 2 * pad - KH) / stride + 1;
    int Wo = (W + 2 * pad - KW) / stride + 1;
    int M  = N * Ho * Wo;
    dim3 grid((M + BM - 1) / BM, Cout / BN);
    adder_conv<BM, BN, TM, TN><<<grid, 128>>>(x, w, out, sc, sh, act,
                                              sum_g, sumsq_g,
                                              N, Cin, H, W, Cout, KH, KW,
                                              stride, pad, Ho, Wo);
}

extern "C" void kernel_launch(void* const* d_in, const int* in_sizes, int n_in,
                              void* d_out, int out_size)
{
    (void)in_sizes; (void)n_in; (void)out_size;
    const float* x = (const float*)d_in[0];
    const float* W[6]; const float* G[6]; const float* B[6];
    for (int i = 0; i < 6; i++) {
        W[i] = (const float*)d_in[1 + 3 * i];
        G[i] = (const float*)d_in[2 + 3 * i];
        B[i] = (const float*)d_in[3 + 3 * i];
    }

    float *bufA, *bufB, *scl, *shf;
    double *sum, *sq;
    cudaGetSymbolAddress((void**)&bufA, g_bufA);
    cudaGetSymbolAddress((void**)&bufB, g_bufB);
    cudaGetSymbolAddress((void**)&scl,  g_scale);
    cudaGetSymbolAddress((void**)&shf,  g_shift);
    cudaGetSymbolAddress((void**)&sum,  g_sum);
    cudaGetSymbolAddress((void**)&sq,   g_sumsq);

    float  *SC[6], *SH[6];
    double *SU[6], *SQ[6];
    for (int i = 0; i < 6; i++) {
        SC[i] = scl + i * 512; SH[i] = shf + i * 512;
        SU[i] = sum + i * 512; SQ[i] = sq  + i * 512;
    }

    const int Nb = 16;
    zero_stats_kernel<<<12, 256>>>();

    // L1: 1x1 512->256, 38x38
    run_conv<64, 128, 8, 8>(x, W[0], bufA, nullptr, nullptr, 0, SU[0], SQ[0],
                            Nb, 512, 38, 38, 256, 1, 1, 1, 0);
    finalize_bn<<<1, 256>>>(SU[0], SQ[0], G[0], B[0], SC[0], SH[0], 256, Nb * 38 * 38);

    // L2: 3x3 256->512, s2 p1 -> 19x19
    run_conv<64, 128, 8, 8>(bufA, W[1], bufB, SC[0], SH[0], 1, SU[1], SQ[1],
                            Nb, 256, 38, 38, 512, 3, 3, 2, 1);
    finalize_bn<<<2, 256>>>(SU[1], SQ[1], G[1], B[1], SC[1], SH[1], 512, Nb * 19 * 19);

    // L3: 1x1 512->128, 19x19
    run_conv<32, 64, 4, 4>(bufB, W[2], bufA, SC[1], SH[1], 1, SU[2], SQ[2],
                           Nb, 512, 19, 19, 128, 1, 1, 1, 0);
    finalize_bn<<<1, 128>>>(SU[2], SQ[2], G[2], B[2], SC[2], SH[2], 128, Nb * 19 * 19);

    // L4: 3x3 128->256, s2 p1 -> 10x10
    run_conv<32, 64, 4, 4>(bufA, W[3], bufB, SC[2], SH[2], 1, SU[3], SQ[3],
                           Nb, 128, 19, 19, 256, 3, 3, 2, 1);
    finalize_bn<<<1, 256>>>(SU[3], SQ[3], G[3], B[3], SC[3], SH[3], 256, Nb * 10 * 10);

    // L5: 1x1 256->128, 10x10
    run_conv<32, 64, 4, 4>(bufB, W[4], bufA, SC[3], SH[3], 1, SU[4], SQ[4],
                           Nb, 256, 10, 10, 128, 1, 1, 1, 0);
    finalize_bn<<<1, 128>>>(SU[4], SQ[4], G[4], B[4], SC[4], SH[4], 128, Nb * 10 * 10);

    // L6: 3x3 128->256, s2 p0 -> 4x4
    run_conv<32, 64, 4, 4>(bufA, W[5], bufB, SC[4], SH[4], 1, SU[5], SQ[5],
                           Nb, 128, 10, 10, 256, 3, 3, 2, 0);
    finalize_bn<<<1, 256>>>(SU[5], SQ[5], G[5], B[5], SC[5], SH[5], 256, Nb * 4 * 4);

    // Final BN + ReLU6 -> d_out  [16, 256, 4, 4]
    int total = Nb * 256 * 4 * 4;
    apply_bn_relu6<<<(total + 255) / 256, 256>>>(bufB, (float*)d_out, SC[5], SH[5],
                                                 total, 4 * 4, 256);
}

// round 4
// speedup vs baseline: 1.6900x; 1.5501x over previous
#include <cuda_runtime.h>

typedef unsigned long long u64;
#define ABS2_MASK 0x7FFFFFFF7FFFFFFFull

// Packed fp32x2 add (sm_103a): one fma-pipe instruction, 2 FP32 adds per lane.
__device__ __forceinline__ u64 addx2(u64 a, u64 b) {
    u64 d;
    asm("add.rn.f32x2 %0, %1, %2;" : "=l"(d) : "l"(a), "l"(b));
    return d;
}

// ---------------- scratch (device globals; no runtime allocation) ----------
__device__ float  g_patch[13565952];            // [K][M_pad] patches, 54.3 MB (max: L2)
__device__ float  g_bufA[16 * 256 * 38 * 38];   // act ping (pre-BN), 23.7 MB
__device__ float  g_bufB[16 * 512 * 19 * 19];   // act pong, 11.8 MB
__device__ float  g_wT[512 * 2304];             // negated transposed weights, 4.7 MB
__device__ double g_sum[6][512];
__device__ double g_sumsq[6][512];
__device__ float  g_scale[6][512];
__device__ float  g_shift[6][512];

__global__ void zero_stats_kernel() {
    int i = blockIdx.x * blockDim.x + threadIdx.x;
    if (i < 6 * 512) {
        (&g_sum[0][0])[i]   = 0.0;
        (&g_sumsq[0][0])[i] = 0.0;
    }
}

__device__ __forceinline__ float act6(float v, float sc, float sh) {
    return fminf(fmaxf(fmaf(v, sc, sh), 0.f), 6.f);
}

// ---- 1x1 layers: NCHW -> [k][M_pad] transpose with BN+ReLU6 fold -----------
__global__ void t1x1_kernel(const float* __restrict__ src, float* __restrict__ P,
                            const float* __restrict__ scale,
                            const float* __restrict__ shift, int do_act,
                            int M, int M_pad, int HW, int Cin)
{
    int k = blockIdx.y;
    int m = blockIdx.x * blockDim.x + threadIdx.x;
    if (m >= M) return;
    int n = m / HW, s = m - n * HW;
    float v = src[(size_t)(n * Cin + k) * HW + s];
    if (do_act) v = act6(v, scale[k], shift[k]);
    P[(size_t)k * M_pad + m] = v;
}

// ---- 3x3 layers: im2col with BN+ReLU6 fold; OOB (padding) -> 0 ------------
__global__ void im2col3x3_kernel(const float* __restrict__ src, float* __restrict__ P,
                                 const float* __restrict__ scale,
                                 const float* __restrict__ shift,
                                 int M, int M_pad, int Cin, int H, int W,
                                 int Ho, int Wo, int stride, int pad)
{
    int k = blockIdx.y;
    int m = blockIdx.x * blockDim.x + threadIdx.x;
    if (m >= M) return;
    int c  = k / 9;
    int r  = k - 9 * c;
    int ky = r / 3;
    int kx = r - 3 * ky;
    int HoWo = Ho * Wo;
    int n  = m / HoWo, s  = m - n * HoWo;
    int oy = s / Wo,   ox = s - oy * Wo;
    int iy = oy * stride - pad + ky;
    int ix = ox * stride - pad + kx;
    float v = 0.f;
    if (iy >= 0 && iy < H && ix >= 0 && ix < W) {
        v = act6(src[((size_t)(n * Cin + c) * H + iy) * W + ix], scale[c], shift[c]);
    }
    P[(size_t)k * M_pad + m] = v;
}

// ---- weights: negate + transpose to [k][Cout] (32x32 smem tiles) ----------
__global__ void wtrans_kernel(const float* __restrict__ w, float* __restrict__ wT,
                              int K, int Cout)
{
    __shared__ float t[32][33];
    int bk  = blockIdx.x * 32;
    int bco = blockIdx.y * 32;
    int tx  = threadIdx.x, ty = threadIdx.y;   // (32, 8)
#pragma unroll
    for (int i = 0; i < 4; i++) {
        int co = bco + ty + i * 8;
        t[ty + i * 8][tx] = -w[(size_t)co * K + bk + tx];
    }
    __syncthreads();
#pragma unroll
    for (int i = 0; i < 4; i++) {
        int k = bk + ty + i * 8;
        wT[(size_t)k * Cout + bco + tx] = t[tx][ty + i * 8];
    }
}

// ---------------------------------------------------------------------------
// Adder GEMM:  pre[m, co] = -sum_k |P[k,m] - W[co,k]|
// P: [K][M_pad] activation patches. Wt: [K][Cout] NEGATED weights.
// Packed f32x2: 2 adjacent m per 64-bit lane; weights duplicated in smem.
// Per-channel sum/sumsq reduced in-warp, atomically added (double).
// ---------------------------------------------------------------------------
template<int BM, int BN, int TM, int TN>
__global__ __launch_bounds__(128, 4)
void adder_gemm(const float* __restrict__ P, const float* __restrict__ Wt,
                float* __restrict__ out,
                double* __restrict__ sum_g, double* __restrict__ sumsq_g,
                int M, int M_pad, int K, int Cout, int HoWo)
{
    constexpr int BK = 16;
    constexpr int NT = 128;
    static_assert(BM / TM == 16 && BN / TN == 8, "thread layout");
    __shared__ float sP[BK][BM];
    __shared__ float sW[BK][2 * BN + 8];

    const int tid = threadIdx.x;
    const int m0  = blockIdx.x * BM;
    const int n0  = blockIdx.y * BN;
    const int txm = tid & 15;
    const int ty  = tid >> 4;
    const int tm0 = txm * TM;
    const int tn0 = ty * TN;

    u64 acc[TM / 2][TN];
#pragma unroll
    for (int i = 0; i < TM / 2; i++)
#pragma unroll
        for (int j = 0; j < TN; j++) acc[i][j] = 0ull;

    const float* pP = P + m0;
    const float* pW = Wt + n0;

    for (int k0 = 0; k0 < K; k0 += BK) {
        // ---- P tile: pure coalesced float4 stream, no index math ----
        constexpr int NP4 = BM / 4;
#pragma unroll
        for (int r = 0; r < (BK * NP4) / NT; r++) {
            int idx = r * NT + tid;
            int lk  = idx / NP4;
            int c4  = idx - lk * NP4;
            float4 v = *reinterpret_cast<const float4*>(pP + (size_t)lk * M_pad + c4 * 4);
            *reinterpret_cast<float4*>(&sP[lk][c4 * 4]) = v;
        }
        // ---- W tile: coalesced load, store duplicated ----
#pragma unroll
        for (int r = 0; r < (BK * BN) / NT; r++) {
            int idx = r * NT + tid;
            int lk  = idx / BN;
            int lco = idx - lk * BN;
            float v = pW[(size_t)lk * Cout + lco];
            *reinterpret_cast<float2*>(&sW[lk][2 * lco]) = make_float2(v, v);
        }
        __syncthreads();

        // ---- compute: addx2 / packed-abs / addx2 ----
#pragma unroll
        for (int kk = 0; kk < BK; kk++) {
            u64 p2[TM / 2];
#pragma unroll
            for (int i = 0; i < TM / 4; i++) {
                ulonglong2 t = *reinterpret_cast<const ulonglong2*>(&sP[kk][tm0 + 4 * i]);
                p2[2 * i]     = t.x;
                p2[2 * i + 1] = t.y;
            }
            u64 w2[TN];
#pragma unroll
            for (int j = 0; j < TN / 2; j++) {
                ulonglong2 t = *reinterpret_cast<const ulonglong2*>(&sW[kk][2 * tn0 + 4 * j]);
                w2[2 * j]     = t.x;
                w2[2 * j + 1] = t.y;
            }
#pragma unroll
            for (int i = 0; i < TM / 2; i++)
#pragma unroll
                for (int j = 0; j < TN; j++) {
                    u64 d = addx2(p2[i], w2[j]) & ABS2_MASK;
                    acc[i][j] = addx2(acc[i][j], d);
                }
        }
        __syncthreads();
        pP += (size_t)BK * M_pad;
        pW += (size_t)BK * Cout;
    }

    // ---- writeback (-acc) + per-channel stats ----
    float s_sum[TN], s_sq[TN];
#pragma unroll
    for (int j = 0; j < TN; j++) { s_sum[j] = 0.f; s_sq[j] = 0.f; }

#pragma unroll
    for (int i = 0; i < TM / 2; i++) {
        int mA = m0 + tm0 + 2 * i;
        int mB = mA + 1;
        bool okA = mA < M, okB = mB < M;
        int nA = 0, sA = 0, nB = 0, sB = 0;
        if (okA) { nA = mA / HoWo; sA = mA - nA * HoWo; }
        if (okB) { nB = mB / HoWo; sB = mB - nB * HoWo; }
#pragma unroll
        for (int j = 0; j < TN; j++) {
            float lo = __uint_as_float((unsigned int)(acc[i][j] & 0xFFFFFFFFull));
            float hi = __uint_as_float((unsigned int)(acc[i][j] >> 32));
            float vA = -lo, vB = -hi;
            int c = n0 + tn0 + j;
            if (okA) {
                out[(size_t)(nA * Cout + c) * HoWo + sA] = vA;
                s_sum[j] += vA; s_sq[j] += vA * vA;
            }
            if (okB) {
                out[(size_t)(nB * Cout + c) * HoWo + sB] = vB;
                s_sum[j] += vB; s_sq[j] += vB * vB;
            }
        }
    }
#pragma unroll
    for (int j = 0; j < TN; j++) {
        float a = s_sum[j], b = s_sq[j];
#pragma unroll
        for (int o = 1; o < 16; o <<= 1) {
            a += __shfl_xor_sync(0xffffffffu, a, o);
            b += __shfl_xor_sync(0xffffffffu, b, o);
        }
        if (txm == 0) {
            int c = n0 + tn0 + j;
            atomicAdd(&sum_g[c],   (double)a);
            atomicAdd(&sumsq_g[c], (double)b);
        }
    }
}

__global__ void finalize_bn(const double* __restrict__ sum_g,
                            const double* __restrict__ sumsq_g,
                            const float* __restrict__ gamma,
                            const float* __restrict__ beta,
                            float* __restrict__ scale,
                            float* __restrict__ shift,
                            int Cout, int cnt)
{
    int c = blockIdx.x * blockDim.x + threadIdx.x;
    if (c < Cout) {
        double mean = sum_g[c] / cnt;
        double var  = sumsq_g[c] / cnt - mean * mean;
        float rstd  = (float)(1.0 / sqrt(var + 1e-5));
        float sc    = gamma[c] * rstd;
        scale[c]    = sc;
        shift[c]    = beta[c] - (float)mean * sc;
    }
}

__global__ void apply_bn_relu6(const float* __restrict__ pre,
                               float* __restrict__ out,
                               const float* __restrict__ scale,
                               const float* __restrict__ shift,
                               int total, int HoWo, int Cout)
{
    int i = blockIdx.x * blockDim.x + threadIdx.x;
    if (i < total) {
        int c = (i / HoWo) % Cout;
        out[i] = act6(pre[i], scale[c], shift[c]);
    }
}

extern "C" void kernel_launch(void* const* d_in, const int* in_sizes, int n_in,
                              void* d_out, int out_size)
{
    (void)in_sizes; (void)n_in; (void)out_size;
    const float* x = (const float*)d_in[0];
    const float* W[6]; const float* G[6]; const float* B[6];
    for (int i = 0; i < 6; i++) {
        W[i] = (const float*)d_in[1 + 3 * i];
        G[i] = (const float*)d_in[2 + 3 * i];
        B[i] = (const float*)d_in[3 + 3 * i];
    }

    float *patch, *bufA, *bufB, *wT, *scl, *shf;
    double *sum, *sq;
    cudaGetSymbolAddress((void**)&patch, g_patch);
    cudaGetSymbolAddress((void**)&bufA,  g_bufA);
    cudaGetSymbolAddress((void**)&bufB,  g_bufB);
    cudaGetSymbolAddress((void**)&wT,    g_wT);
    cudaGetSymbolAddress((void**)&scl,   g_scale);
    cudaGetSymbolAddress((void**)&shf,   g_shift);
    cudaGetSymbolAddress((void**)&sum,   g_sum);
    cudaGetSymbolAddress((void**)&sq,    g_sumsq);

    float  *SC[6], *SH[6];
    double *SU[6], *SQ[6];
    for (int i = 0; i < 6; i++) {
        SC[i] = scl + i * 512; SH[i] = shf + i * 512;
        SU[i] = sum + i * 512; SQ[i] = sq  + i * 512;
    }

    zero_stats_kernel<<<12, 256>>>();

    // ---------------- L1: 1x1 512->256, 38x38 (no input act) ----------------
    {
        const int M = 23104, M_pad = 23168, K = 512, Cout = 256, HW = 1444;
        t1x1_kernel<<<dim3((M + 255) / 256, K), 256>>>(x, patch, nullptr, nullptr, 0, M, M_pad, HW, K);
        wtrans_kernel<<<dim3(K / 32, Cout / 32), dim3(32, 8)>>>(W[0], wT, K, Cout);
        adder_gemm<128, 64, 8, 8><<<dim3(M_pad / 128, Cout / 64), 128>>>(
            patch, wT, bufA, SU[0], SQ[0], M, M_pad, K, Cout, HW);
        finalize_bn<<<1, 256>>>(SU[0], SQ[0], G[0], B[0], SC[0], SH[0], Cout, M);
    }
    // ---------------- L2: 3x3 256->512 s2 p1, 38x38 -> 19x19 ----------------
    {
        const int M = 5776, M_pad = 5888, K = 2304, Cout = 512, HoWo = 361;
        im2col3x3_kernel<<<dim3((M + 255) / 256, K), 256>>>(
            bufA, patch, SC[0], SH[0], M, M_pad, 256, 38, 38, 19, 19, 2, 1);
        wtrans_kernel<<<dim3(K / 32, Cout / 32), dim3(32, 8)>>>(W[1], wT, K, Cout);
        adder_gemm<128, 64, 8, 8><<<dim3(M_pad / 128, Cout / 64), 128>>>(
            patch, wT, bufB, SU[1], SQ[1], M, M_pad, K, Cout, HoWo);
        finalize_bn<<<2, 256>>>(SU[1], SQ[1], G[1], B[1], SC[1], SH[1], Cout, M);
    }
    // ---------------- L3: 1x1 512->128, 19x19 ----------------
    {
        const int M = 5776, M_pad = 5824, K = 512, Cout = 128, HW = 361;
        t1x1_kernel<<<dim3((M + 255) / 256, K), 256>>>(bufB, patch, SC[1], SH[1], 1, M, M_pad, HW, K);
        wtrans_kernel<<<dim3(K / 32, Cout / 32), dim3(32, 8)>>>(W[2], wT, K, Cout);
        adder_gemm<64, 64, 4, 8><<<dim3(M_pad / 64, Cout / 64), 128>>>(
            patch, wT, bufA, SU[2], SQ[2], M, M_pad, K, Cout, HW);
        finalize_bn<<<1, 128>>>(SU[2], SQ[2], G[2], B[2], SC[2], SH[2], Cout, M);
    }
    // ---------------- L4: 3x3 128->256 s2 p1, 19x19 -> 10x10 ----------------
    {
        const int M = 1600, M_pad = 1600, K = 1152, Cout = 256, HoWo = 100;
        im2col3x3_kernel<<<dim3((M + 255) / 256, K), 256>>>(
            bufA, patch, SC[2], SH[2], M, M_pad, 128, 19, 19, 10, 10, 2, 1);
        wtrans_kernel<<<dim3(K / 32, Cout / 32), dim3(32, 8)>>>(W[3], wT, K, Cout);
        adder_gemm<64, 64, 4, 8><<<dim3(M_pad / 64, Cout / 64), 128>>>(
            patch, wT, bufB, SU[3], SQ[3], M, M_pad, K, Cout, HoWo);
        finalize_bn<<<1, 256>>>(SU[3], SQ[3], G[3], B[3], SC[3], SH[3], Cout, M);
    }
    // ---------------- L5: 1x1 256->128, 10x10 ----------------
    {
        const int M = 1600, M_pad = 1600, K = 256, Cout = 128, HW = 100;
        t1x1_kernel<<<dim3((M + 255) / 256, K), 256>>>(bufB, patch, SC[3], SH[3], 1, M, M_pad, HW, K);
        wtrans_kernel<<<dim3(K / 32, Cout / 32), dim3(32, 8)>>>(W[4], wT, K, Cout);
        adder_gemm<64, 64, 4, 8><<<dim3(M_pad / 64, Cout / 64), 128>>>(
            patch, wT, bufA, SU[4], SQ[4], M, M_pad, K, Cout, HW);
        finalize_bn<<<1, 128>>>(SU[4], SQ[4], G[4], B[4], SC[4], SH[4], Cout, M);
    }
    // ---------------- L6: 3x3 128->256 s2 p0, 10x10 -> 4x4 ----------------
    {
        const int M = 256, M_pad = 256, K = 1152, Cout = 256, HoWo = 16;
        im2col3x3_kernel<<<dim3(1, K), 256>>>(
            bufA, patch, SC[4], SH[4], M, M_pad, 128, 10, 10, 4, 4, 2, 0);
        wtrans_kernel<<<dim3(K / 32, Cout / 32), dim3(32, 8)>>>(W[5], wT, K, Cout);
        adder_gemm<64, 64, 4, 8><<<dim3(M_pad / 64, Cout / 64), 128>>>(
            patch, wT, bufB, SU[5], SQ[5], M, M_pad, K, Cout, HoWo);
        finalize_bn<<<1, 256>>>(SU[5], SQ[5], G[5], B[5], SC[5], SH[5], Cout, M);
    }

    // Final BN + ReLU6 -> d_out  [16, 256, 4, 4]
    int total = 16 * 256 * 4 * 4;
    apply_bn_relu6<<<(total + 255) / 256, 256>>>(bufB, (float*)d_out, SC[5], SH[5],
                                                 total, 16, 256);
}

// round 5
// speedup vs baseline: 1.8923x; 1.1197x over previous
#include <cuda_runtime.h>

typedef unsigned long long u64;
#define ABS2_MASK 0x7FFFFFFF7FFFFFFFull

// Packed fp32x2 add (sm_103a): one fma-pipe instruction, 2 FP32 adds per lane.
__device__ __forceinline__ u64 addx2(u64 a, u64 b) {
    u64 d;
    asm("add.rn.f32x2 %0, %1, %2;" : "=l"(d) : "l"(a), "l"(b));
    return d;
}

__device__ __forceinline__ void cp_async16(unsigned smem_addr, const void* gptr) {
    asm volatile("cp.async.cg.shared.global [%0], [%1], 16;" :: "r"(smem_addr), "l"(gptr));
}
__device__ __forceinline__ void cp_commit() {
    asm volatile("cp.async.commit_group;");
}
template<int N>
__device__ __forceinline__ void cp_wait() {
    asm volatile("cp.async.wait_group %0;" :: "n"(N));
}

// ---------------- scratch (device globals; no runtime allocation) ----------
__device__ float  g_patch[13565952];            // [K][M_pad] patches (max 54.3 MB)
__device__ float  g_bufA[16 * 256 * 38 * 38];   // act ping (pre-BN), 23.7 MB
__device__ float  g_bufB[16 * 512 * 19 * 19];   // act pong, 11.8 MB
__device__ float  g_wT[2304 * 1024];            // negated, transposed, DUPLICATED weights
__device__ double g_sum[6][512];
__device__ double g_sumsq[6][512];
__device__ float  g_scale[6][512];
__device__ float  g_shift[6][512];

__global__ void zero_stats_kernel() {
    int i = blockIdx.x * blockDim.x + threadIdx.x;
    if (i < 6 * 512) {
        (&g_sum[0][0])[i]   = 0.0;
        (&g_sumsq[0][0])[i] = 0.0;
    }
}

__device__ __forceinline__ float act6(float v, float sc, float sh) {
    return fminf(fmaxf(fmaf(v, sc, sh), 0.f), 6.f);
}

// ---- 1x1 layers: NCHW -> [k][M_pad] transpose with BN+ReLU6 fold -----------
__global__ void t1x1_kernel(const float* __restrict__ src, float* __restrict__ P,
                            const float* __restrict__ scale,
                            const float* __restrict__ shift, int do_act,
                            int M, int M_pad, int HW, int Cin)
{
    int k = blockIdx.y;
    int m = blockIdx.x * blockDim.x + threadIdx.x;
    if (m >= M) return;
    int n = m / HW, s = m - n * HW;
    float v = src[(size_t)(n * Cin + k) * HW + s];
    if (do_act) v = act6(v, scale[k], shift[k]);
    P[(size_t)k * M_pad + m] = v;
}

// ---- 3x3 layers: im2col with BN+ReLU6 fold; OOB (padding) -> 0 ------------
__global__ void im2col3x3_kernel(const float* __restrict__ src, float* __restrict__ P,
                                 const float* __restrict__ scale,
                                 const float* __restrict__ shift,
                                 int M, int M_pad, int Cin, int H, int W,
                                 int Ho, int Wo, int stride, int pad)
{
    int k = blockIdx.y;
    int m = blockIdx.x * blockDim.x + threadIdx.x;
    if (m >= M) return;
    int c  = k / 9;
    int r  = k - 9 * c;
    int ky = r / 3;
    int kx = r - 3 * ky;
    int HoWo = Ho * Wo;
    int n  = m / HoWo, s  = m - n * HoWo;
    int oy = s / Wo,   ox = s - oy * Wo;
    int iy = oy * stride - pad + ky;
    int ix = ox * stride - pad + kx;
    float v = 0.f;
    if (iy >= 0 && iy < H && ix >= 0 && ix < W) {
        v = act6(src[((size_t)(n * Cin + c) * H + iy) * W + ix], scale[c], shift[c]);
    }
    P[(size_t)k * M_pad + m] = v;
}

// ---- weights: negate + transpose + DUPLICATE to [k][2*Cout] ---------------
__global__ void wtrans_kernel(const float* __restrict__ w, float* __restrict__ wT,
                              int K, int Cout)
{
    __shared__ float t[32][33];
    int bk  = blockIdx.x * 32;
    int bco = blockIdx.y * 32;
    int tx  = threadIdx.x, ty = threadIdx.y;   // (32, 8)
#pragma unroll
    for (int i = 0; i < 4; i++) {
        int co = bco + ty + i * 8;
        t[ty + i * 8][tx] = -w[(size_t)co * K + bk + tx];
    }
    __syncthreads();
#pragma unroll
    for (int i = 0; i < 4; i++) {
        int k = bk + ty + i * 8;
        float v = t[tx][ty + i * 8];
        *reinterpret_cast<float2*>(&wT[(size_t)k * 2 * Cout + 2 * (bco + tx)]) =
            make_float2(v, v);
    }
}

// ---------------------------------------------------------------------------
// Adder GEMM:  pre[m, co] = -sum_k |P[k,m] - W[co,k]|
// P: [K][M_pad]. Wd: [K][2*Cout] negated duplicated weights.
// Double-buffered cp.async pipeline: both tiles loaded verbatim with LDGSTS,
// tile t+1 in flight while computing tile t. Per-channel stats fused.
// ---------------------------------------------------------------------------
template<int BM, int BN, int TM, int TN>
__global__ __launch_bounds__(128, 4)
void adder_gemm(const float* __restrict__ P, const float* __restrict__ Wd,
                float* __restrict__ out,
                double* __restrict__ sum_g, double* __restrict__ sumsq_g,
                int M, int M_pad, int K, int Cout, int HoWo)
{
    constexpr int BK = 16;
    constexpr int NT = 128;
    static_assert(BM / TM == 16 && BN / TN == 8, "thread layout");
    __shared__ float sP[2][BK][BM];
    __shared__ float sW[2][BK][2 * BN];

    const int tid = threadIdx.x;
    const int m0  = blockIdx.x * BM;
    const int n0  = blockIdx.y * BN;
    const int txm = tid & 15;
    const int ty  = tid >> 4;
    const int tm0 = txm * TM;
    const int tn0 = ty * TN;

    u64 acc[TM / 2][TN];
#pragma unroll
    for (int i = 0; i < TM / 2; i++)
#pragma unroll
        for (int j = 0; j < TN; j++) acc[i][j] = 0ull;

    const float* gP = P  + m0;                      // + k*M_pad
    const float* gW = Wd + 2 * n0;                  // + k*2*Cout
    const int nTiles = K / BK;

    // per-thread cp.async assignments (all in-bounds by construction)
    constexpr int P16 = BK * BM / 4;                // 16B chunks in P tile
    constexpr int W16 = BK * 2 * BN / 4;            // 16B chunks in W tile
    constexpr int PR  = P16 / NT;                   // chunks per thread
    constexpr int WR  = W16 / NT;

    auto issue_tile = [&](int t, int buf) {
        const float* bP = gP + (size_t)t * BK * M_pad;
        const float* bW = gW + (size_t)t * BK * 2 * Cout;
#pragma unroll
        for (int r = 0; r < PR; r++) {
            int idx = r * NT + tid;
            int lk  = idx / (BM / 4);
            int c4  = idx - lk * (BM / 4);
            cp_async16((unsigned)__cvta_generic_to_shared(&sP[buf][lk][c4 * 4]),
                       bP + (size_t)lk * M_pad + c4 * 4);
        }
#pragma unroll
        for (int r = 0; r < WR; r++) {
            int idx = r * NT + tid;
            int lk  = idx / (2 * BN / 4);
            int c4  = idx - lk * (2 * BN / 4);
            cp_async16((unsigned)__cvta_generic_to_shared(&sW[buf][lk][c4 * 4]),
                       bW + (size_t)lk * 2 * Cout + c4 * 4);
        }
        cp_commit();
    };

    issue_tile(0, 0);

    for (int t = 0; t < nTiles; t++) {
        int buf = t & 1;
        if (t + 1 < nTiles) {
            issue_tile(t + 1, buf ^ 1);
            cp_wait<1>();
        } else {
            cp_wait<0>();
        }
        __syncthreads();

#pragma unroll
        for (int kk = 0; kk < BK; kk++) {
            u64 p2[TM / 2];
#pragma unroll
            for (int i = 0; i < TM / 4; i++) {
                ulonglong2 v = *reinterpret_cast<const ulonglong2*>(&sP[buf][kk][tm0 + 4 * i]);
                p2[2 * i]     = v.x;
                p2[2 * i + 1] = v.y;
            }
            u64 w2[TN];
#pragma unroll
            for (int j = 0; j < TN / 2; j++) {
                ulonglong2 v = *reinterpret_cast<const ulonglong2*>(&sW[buf][kk][2 * tn0 + 4 * j]);
                w2[2 * j]     = v.x;
                w2[2 * j + 1] = v.y;
            }
#pragma unroll
            for (int i = 0; i < TM / 2; i++)
#pragma unroll
                for (int j = 0; j < TN; j++) {
                    u64 d = addx2(p2[i], w2[j]) & ABS2_MASK;
                    acc[i][j] = addx2(acc[i][j], d);
                }
        }
        __syncthreads();
    }

    // ---- writeback (-acc) + per-channel stats ----
    float s_sum[TN], s_sq[TN];
#pragma unroll
    for (int j = 0; j < TN; j++) { s_sum[j] = 0.f; s_sq[j] = 0.f; }

#pragma unroll
    for (int i = 0; i < TM / 2; i++) {
        int mA = m0 + tm0 + 2 * i;
        int mB = mA + 1;
        bool okA = mA < M, okB = mB < M;
        int nA = 0, sA = 0, nB = 0, sB = 0;
        if (okA) { nA = mA / HoWo; sA = mA - nA * HoWo; }
        if (okB) { nB = mB / HoWo; sB = mB - nB * HoWo; }
#pragma unroll
        for (int j = 0; j < TN; j++) {
            float lo = __uint_as_float((unsigned int)(acc[i][j] & 0xFFFFFFFFull));
            float hi = __uint_as_float((unsigned int)(acc[i][j] >> 32));
            float vA = -lo, vB = -hi;
            int c = n0 + tn0 + j;
            if (okA) {
                out[(size_t)(nA * Cout + c) * HoWo + sA] = vA;
                s_sum[j] += vA; s_sq[j] += vA * vA;
            }
            if (okB) {
                out[(size_t)(nB * Cout + c) * HoWo + sB] = vB;
                s_sum[j] += vB; s_sq[j] += vB * vB;
            }
        }
    }
#pragma unroll
    for (int j = 0; j < TN; j++) {
        float a = s_sum[j], b = s_sq[j];
#pragma unroll
        for (int o = 1; o < 16; o <<= 1) {
            a += __shfl_xor_sync(0xffffffffu, a, o);
            b += __shfl_xor_sync(0xffffffffu, b, o);
        }
        if (txm == 0) {
            int c = n0 + tn0 + j;
            atomicAdd(&sum_g[c],   (double)a);
            atomicAdd(&sumsq_g[c], (double)b);
        }
    }
}

__global__ void finalize_bn(const double* __restrict__ sum_g,
                            const double* __restrict__ sumsq_g,
                            const float* __restrict__ gamma,
                            const float* __restrict__ beta,
                            float* __restrict__ scale,
                            float* __restrict__ shift,
                            int Cout, int cnt)
{
    int c = blockIdx.x * blockDim.x + threadIdx.x;
    if (c < Cout) {
        double mean = sum_g[c] / cnt;
        double var  = sumsq_g[c] / cnt - mean * mean;
        float rstd  = (float)(1.0 / sqrt(var + 1e-5));
        float sc    = gamma[c] * rstd;
        scale[c]    = sc;
        shift[c]    = beta[c] - (float)mean * sc;
    }
}

__global__ void apply_bn_relu6(const float* __restrict__ pre,
                               float* __restrict__ out,
                               const float* __restrict__ scale,
                               const float* __restrict__ shift,
                               int total, int HoWo, int Cout)
{
    int i = blockIdx.x * blockDim.x + threadIdx.x;
    if (i < total) {
        int c = (i / HoWo) % Cout;
        out[i] = act6(pre[i], scale[c], shift[c]);
    }
}

extern "C" void kernel_launch(void* const* d_in, const int* in_sizes, int n_in,
                              void* d_out, int out_size)
{
    (void)in_sizes; (void)n_in; (void)out_size;
    const float* x = (const float*)d_in[0];
    const float* W[6]; const float* G[6]; const float* B[6];
    for (int i = 0; i < 6; i++) {
        W[i] = (const float*)d_in[1 + 3 * i];
        G[i] = (const float*)d_in[2 + 3 * i];
        B[i] = (const float*)d_in[3 + 3 * i];
    }

    float *patch, *bufA, *bufB, *wT, *scl, *shf;
    double *sum, *sq;
    cudaGetSymbolAddress((void**)&patch, g_patch);
    cudaGetSymbolAddress((void**)&bufA,  g_bufA);
    cudaGetSymbolAddress((void**)&bufB,  g_bufB);
    cudaGetSymbolAddress((void**)&wT,    g_wT);
    cudaGetSymbolAddress((void**)&scl,   g_scale);
    cudaGetSymbolAddress((void**)&shf,   g_shift);
    cudaGetSymbolAddress((void**)&sum,   g_sum);
    cudaGetSymbolAddress((void**)&sq,    g_sumsq);

    float  *SC[6], *SH[6];
    double *SU[6], *SQ[6];
    for (int i = 0; i < 6; i++) {
        SC[i] = scl + i * 512; SH[i] = shf + i * 512;
        SU[i] = sum + i * 512; SQ[i] = sq  + i * 512;
    }

    zero_stats_kernel<<<12, 256>>>();

    // ---------------- L1: 1x1 512->256, 38x38 (no input act) ----------------
    {
        const int M = 23104, M_pad = 23168, K = 512, Cout = 256, HW = 1444;
        t1x1_kernel<<<dim3((M + 255) / 256, K), 256>>>(x, patch, nullptr, nullptr, 0, M, M_pad, HW, K);
        wtrans_kernel<<<dim3(K / 32, Cout / 32), dim3(32, 8)>>>(W[0], wT, K, Cout);
        adder_gemm<128, 64, 8, 8><<<dim3(M_pad / 128, Cout / 64), 128>>>(
            patch, wT, bufA, SU[0], SQ[0], M, M_pad, K, Cout, HW);
        finalize_bn<<<1, 256>>>(SU[0], SQ[0], G[0], B[0], SC[0], SH[0], Cout, M);
    }
    // ---------------- L2: 3x3 256->512 s2 p1, 38x38 -> 19x19 ----------------
    {
        const int M = 5776, M_pad = 5888, K = 2304, Cout = 512, HoWo = 361;
        im2col3x3_kernel<<<dim3((M + 255) / 256, K), 256>>>(
            bufA, patch, SC[0], SH[0], M, M_pad, 256, 38, 38, 19, 19, 2, 1);
        wtrans_kernel<<<dim3(K / 32, Cout / 32), dim3(32, 8)>>>(W[1], wT, K, Cout);
        adder_gemm<128, 64, 8, 8><<<dim3(M_pad / 128, Cout / 64), 128>>>(
            patch, wT, bufB, SU[1], SQ[1], M, M_pad, K, Cout, HoWo);
        finalize_bn<<<2, 256>>>(SU[1], SQ[1], G[1], B[1], SC[1], SH[1], Cout, M);
    }
    // ---------------- L3: 1x1 512->128, 19x19 ----------------
    {
        const int M = 5776, M_pad = 5824, K = 512, Cout = 128, HW = 361;
        t1x1_kernel<<<dim3((M + 255) / 256, K), 256>>>(bufB, patch, SC[1], SH[1], 1, M, M_pad, HW, K);
        wtrans_kernel<<<dim3(K / 32, Cout / 32), dim3(32, 8)>>>(W[2], wT, K, Cout);
        adder_gemm<64, 64, 4, 8><<<dim3(M_pad / 64, Cout / 64), 128>>>(
            patch, wT, bufA, SU[2], SQ[2], M, M_pad, K, Cout, HW);
        finalize_bn<<<1, 128>>>(SU[2], SQ[2], G[2], B[2], SC[2], SH[2], Cout, M);
    }
    // ---------------- L4: 3x3 128->256 s2 p1, 19x19 -> 10x10 ----------------
    {
        const int M = 1600, M_pad = 1600, K = 1152, Cout = 256, HoWo = 100;
        im2col3x3_kernel<<<dim3((M + 255) / 256, K), 256>>>(
            bufA, patch, SC[2], SH[2], M, M_pad, 128, 19, 19, 10, 10, 2, 1);
        wtrans_kernel<<<dim3(K / 32, Cout / 32), dim3(32, 8)>>>(W[3], wT, K, Cout);
        adder_gemm<64, 64, 4, 8><<<dim3(M_pad / 64, Cout / 64), 128>>>(
            patch, wT, bufB, SU[3], SQ[3], M, M_pad, K, Cout, HoWo);
        finalize_bn<<<1, 256>>>(SU[3], SQ[3], G[3], B[3], SC[3], SH[3], Cout, M);
    }
    // ---------------- L5: 1x1 256->128, 10x10 ----------------
    {
        const int M = 1600, M_pad = 1600, K = 256, Cout = 128, HW = 100;
        t1x1_kernel<<<dim3((M + 255) / 256, K), 256>>>(bufB, patch, SC[3], SH[3], 1, M, M_pad, HW, K);
        wtrans_kernel<<<dim3(K / 32, Cout / 32), dim3(32, 8)>>>(W[4], wT, K, Cout);
        adder_gemm<64, 64, 4, 8><<<dim3(M_pad / 64, Cout / 64), 128>>>(
            patch, wT, bufA, SU[4], SQ[4], M, M_pad, K, Cout, HW);
        finalize_bn<<<1, 128>>>(SU[4], SQ[4], G[4], B[4], SC[4], SH[4], Cout, M);
    }
    // ---------------- L6: 3x3 128->256 s2 p0, 10x10 -> 4x4 ----------------
    {
        const int M = 256, M_pad = 256, K = 1152, Cout = 256, HoWo = 16;
        im2col3x3_kernel<<<dim3(1, K), 256>>>(
            bufA, patch, SC[4], SH[4], M, M_pad, 128, 10, 10, 4, 4, 2, 0);
        wtrans_kernel<<<dim3(K / 32, Cout / 32), dim3(32, 8)>>>(W[5], wT, K, Cout);
        adder_gemm<64, 64, 4, 8><<<dim3(M_pad / 64, Cout / 64), 128>>>(
            patch, wT, bufB, SU[5], SQ[5], M, M_pad, K, Cout, HoWo);
        finalize_bn<<<1, 256>>>(SU[5], SQ[5], G[5], B[5], SC[5], SH[5], Cout, M);
    }

    // Final BN + ReLU6 -> d_out  [16, 256, 4, 4]
    int total = 16 * 256 * 4 * 4;
    apply_bn_relu6<<<(total + 255) / 256, 256>>>(bufB, (float*)d_out, SC[5], SH[5],
                                                 total, 16, 256);
}

// round 6
// speedup vs baseline: 1.9115x; 1.0101x over previous
#include <cuda_runtime.h>

typedef unsigned long long u64;
#define ABS2_MASK 0x7FFFFFFF7FFFFFFFull

// Packed fp32x2 add (sm_103a): one fma-pipe instruction, 2 FP32 adds per lane.
__device__ __forceinline__ u64 addx2(u64 a, u64 b) {
    u64 d;
    asm("add.rn.f32x2 %0, %1, %2;" : "=l"(d) : "l"(a), "l"(b));
    return d;
}

__device__ __forceinline__ void cp_async16(unsigned smem_addr, const void* gptr) {
    asm volatile("cp.async.cg.shared.global [%0], [%1], 16;" :: "r"(smem_addr), "l"(gptr));
}
__device__ __forceinline__ void cp_commit() {
    asm volatile("cp.async.commit_group;");
}
template<int N>
__device__ __forceinline__ void cp_wait() {
    asm volatile("cp.async.wait_group %0;" :: "n"(N));
}

// ---------------- scratch (device globals; no runtime allocation) ----------
__device__ float  g_patch[13565952];            // [K][M_pad] patches (max 54.3 MB)
__device__ float  g_bufA[16 * 256 * 38 * 38];   // act ping (pre-BN), 23.7 MB
__device__ float  g_bufB[16 * 512 * 19 * 19];   // act pong, 11.8 MB
__device__ float  g_wT[2304 * 1024];            // negated, transposed, DUPLICATED weights
__device__ double g_sum[6][512];
__device__ double g_sumsq[6][512];
__device__ float  g_scale[6][512];
__device__ float  g_shift[6][512];

__global__ void zero_stats_kernel() {
    int i = blockIdx.x * blockDim.x + threadIdx.x;
    if (i < 6 * 512) {
        (&g_sum[0][0])[i]   = 0.0;
        (&g_sumsq[0][0])[i] = 0.0;
    }
}

__device__ __forceinline__ float act6(float v, float sc, float sh) {
    return fminf(fmaxf(fmaf(v, sc, sh), 0.f), 6.f);
}

// ---- 1x1 layers: NCHW -> [k][M_pad] transpose with BN+ReLU6 fold -----------
__global__ void t1x1_kernel(const float* __restrict__ src, float* __restrict__ P,
                            const float* __restrict__ scale,
                            const float* __restrict__ shift, int do_act,
                            int M, int M_pad, int HW, int Cin)
{
    int k = blockIdx.y;
    int m = blockIdx.x * blockDim.x + threadIdx.x;
    if (m >= M) return;
    int n = m / HW, s = m - n * HW;
    float v = src[(size_t)(n * Cin + k) * HW + s];
    if (do_act) v = act6(v, scale[k], shift[k]);
    P[(size_t)k * M_pad + m] = v;
}

// ---- 3x3 layers: im2col with BN+ReLU6 fold; OOB (padding) -> 0 ------------
__global__ void im2col3x3_kernel(const float* __restrict__ src, float* __restrict__ P,
                                 const float* __restrict__ scale,
                                 const float* __restrict__ shift,
                                 int M, int M_pad, int Cin, int H, int W,
                                 int Ho, int Wo, int stride, int pad)
{
    int k = blockIdx.y;
    int m = blockIdx.x * blockDim.x + threadIdx.x;
    if (m >= M) return;
    int c  = k / 9;
    int r  = k - 9 * c;
    int ky = r / 3;
    int kx = r - 3 * ky;
    int HoWo = Ho * Wo;
    int n  = m / HoWo, s  = m - n * HoWo;
    int oy = s / Wo,   ox = s - oy * Wo;
    int iy = oy * stride - pad + ky;
    int ix = ox * stride - pad + kx;
    float v = 0.f;
    if (iy >= 0 && iy < H && ix >= 0 && ix < W) {
        v = act6(src[((size_t)(n * Cin + c) * H + iy) * W + ix], scale[c], shift[c]);
    }
    P[(size_t)k * M_pad + m] = v;
}

// ---- weights: negate + transpose + DUPLICATE to [k][2*Cout] ---------------
__global__ void wtrans_kernel(const float* __restrict__ w, float* __restrict__ wT,
                              int K, int Cout)
{
    __shared__ float t[32][33];
    int bk  = blockIdx.x * 32;
    int bco = blockIdx.y * 32;
    int tx  = threadIdx.x, ty = threadIdx.y;   // (32, 8)
#pragma unroll
    for (int i = 0; i < 4; i++) {
        int co = bco + ty + i * 8;
        t[ty + i * 8][tx] = -w[(size_t)co * K + bk + tx];
    }
    __syncthreads();
#pragma unroll
    for (int i = 0; i < 4; i++) {
        int k = bk + ty + i * 8;
        float v = t[tx][ty + i * 8];
        *reinterpret_cast<float2*>(&wT[(size_t)k * 2 * Cout + 2 * (bco + tx)]) =
            make_float2(v, v);
    }
}

// ---------------------------------------------------------------------------
// Adder GEMM:  pre[m, co] = -sum_k |P[k,m] - W[co,k]|
// P: [K][M_pad]. Wd: [K][2*Cout] negated duplicated weights.
// cp.async double-buffered. Conflict-free sP reads: each thread owns two
// 4-float chunks at txm*4 and BM/2+txm*4 (quarter-warp LDS.128 spans all
// 32 banks). Per-channel stats fused into epilogue.
// ---------------------------------------------------------------------------
template<int BM, int BN, int TM, int TN, int MAXB>
__global__ __launch_bounds__(128, MAXB)
void adder_gemm(const float* __restrict__ P, const float* __restrict__ Wd,
                float* __restrict__ out,
                double* __restrict__ sum_g, double* __restrict__ sumsq_g,
                int M, int M_pad, int K, int Cout, int HoWo)
{
    constexpr int BK = 16;
    constexpr int NT = 128;
    static_assert(BM / TM == 16 && BN / TN == 8, "thread layout");
    static_assert(TM == 4 || TM == 8, "TM");
    __shared__ float sP[2][BK][BM];
    __shared__ float sW[2][BK][2 * BN];

    const int tid = threadIdx.x;
    const int m0  = blockIdx.x * BM;
    const int n0  = blockIdx.y * BN;
    const int txm = tid & 15;
    const int ty  = tid >> 4;
    const int tn0 = ty * TN;

    u64 acc[TM / 2][TN];
#pragma unroll
    for (int i = 0; i < TM / 2; i++)
#pragma unroll
        for (int j = 0; j < TN; j++) acc[i][j] = 0ull;

    const float* gP = P  + m0;
    const float* gW = Wd + 2 * n0;
    const int nTiles = K / BK;

    constexpr int PR = (BK * BM / 4) / NT;
    constexpr int WR = (BK * 2 * BN / 4) / NT;

    auto issue_tile = [&](int t, int buf) {
        const float* bP = gP + (size_t)t * BK * M_pad;
        const float* bW = gW + (size_t)t * BK * 2 * Cout;
#pragma unroll
        for (int r = 0; r < PR; r++) {
            int idx = r * NT + tid;
            int lk  = idx / (BM / 4);
            int c4  = idx - lk * (BM / 4);
            cp_async16((unsigned)__cvta_generic_to_shared(&sP[buf][lk][c4 * 4]),
                       bP + (size_t)lk * M_pad + c4 * 4);
        }
#pragma unroll
        for (int r = 0; r < WR; r++) {
            int idx = r * NT + tid;
            int lk  = idx / (2 * BN / 4);
            int c4  = idx - lk * (2 * BN / 4);
            cp_async16((unsigned)__cvta_generic_to_shared(&sW[buf][lk][c4 * 4]),
                       bW + (size_t)lk * 2 * Cout + c4 * 4);
        }
        cp_commit();
    };

    issue_tile(0, 0);

    for (int t = 0; t < nTiles; t++) {
        int buf = t & 1;
        if (t + 1 < nTiles) {
            issue_tile(t + 1, buf ^ 1);
            cp_wait<1>();
        } else {
            cp_wait<0>();
        }
        __syncthreads();

#pragma unroll
        for (int kk = 0; kk < BK; kk++) {
            // conflict-free P chunks: [txm*4 .. +4) and [BM/2 + txm*4 .. +4)
            u64 p2[TM / 2];
            {
                ulonglong2 v = *reinterpret_cast<const ulonglong2*>(&sP[buf][kk][txm * 4]);
                p2[0] = v.x; p2[1] = v.y;
                if (TM == 8) {
                    ulonglong2 u = *reinterpret_cast<const ulonglong2*>(&sP[buf][kk][BM / 2 + txm * 4]);
                    p2[2] = u.x; p2[3] = u.y;
                }
            }
            // W in two halves: fewer live registers, scheduler slack
#pragma unroll
            for (int h = 0; h < 2; h++) {
                u64 w2[TN / 2];
                ulonglong2 a = *reinterpret_cast<const ulonglong2*>(&sW[buf][kk][2 * tn0 + 8 * h]);
                ulonglong2 b = *reinterpret_cast<const ulonglong2*>(&sW[buf][kk][2 * tn0 + 8 * h + 4]);
                w2[0] = a.x; w2[1] = a.y; w2[2] = b.x; w2[3] = b.y;
#pragma unroll
                for (int i = 0; i < TM / 2; i++)
#pragma unroll
                    for (int j = 0; j < TN / 2; j++) {
                        u64 d = addx2(p2[i], w2[j]) & ABS2_MASK;
                        acc[i][4 * h + j] = addx2(acc[i][4 * h + j], d);
                    }
            }
        }
        __syncthreads();
    }

    // ---- writeback (-acc) + per-channel stats ----
    // acc[i][j] covers m = m0 + (i>>1)*(BM/2) + txm*4 + (i&1)*2 + {0,1}
    float s_sum[TN], s_sq[TN];
#pragma unroll
    for (int j = 0; j < TN; j++) { s_sum[j] = 0.f; s_sq[j] = 0.f; }

#pragma unroll
    for (int i = 0; i < TM / 2; i++) {
        int mA = m0 + (i >> 1) * (BM / 2) + txm * 4 + (i & 1) * 2;
        int mB = mA + 1;
        bool okA = mA < M, okB = mB < M;
        int nA = 0, sA = 0, nB = 0, sB = 0;
        if (okA) { nA = mA / HoWo; sA = mA - nA * HoWo; }
        if (okB) { nB = mB / HoWo; sB = mB - nB * HoWo; }
#pragma unroll
        for (int j = 0; j < TN; j++) {
            float lo = __uint_as_float((unsigned int)(acc[i][j] & 0xFFFFFFFFull));
            float hi = __uint_as_float((unsigned int)(acc[i][j] >> 32));
            float vA = -lo, vB = -hi;
            int c = n0 + tn0 + j;
            if (okA) {
                out[(size_t)(nA * Cout + c) * HoWo + sA] = vA;
                s_sum[j] += vA; s_sq[j] += vA * vA;
            }
            if (okB) {
                out[(size_t)(nB * Cout + c) * HoWo + sB] = vB;
                s_sum[j] += vB; s_sq[j] += vB * vB;
            }
        }
    }
#pragma unroll
    for (int j = 0; j < TN; j++) {
        float a = s_sum[j], b = s_sq[j];
#pragma unroll
        for (int o = 1; o < 16; o <<= 1) {
            a += __shfl_xor_sync(0xffffffffu, a, o);
            b += __shfl_xor_sync(0xffffffffu, b, o);
        }
        if (txm == 0) {
            int c = n0 + tn0 + j;
            atomicAdd(&sum_g[c],   (double)a);
            atomicAdd(&sumsq_g[c], (double)b);
        }
    }
}

__global__ void finalize_bn(const double* __restrict__ sum_g,
                            const double* __restrict__ sumsq_g,
                            const float* __restrict__ gamma,
                            const float* __restrict__ beta,
                            float* __restrict__ scale,
                            float* __restrict__ shift,
                            int Cout, int cnt)
{
    int c = blockIdx.x * blockDim.x + threadIdx.x;
    if (c < Cout) {
        double mean = sum_g[c] / cnt;
        double var  = sumsq_g[c] / cnt - mean * mean;
        float rstd  = (float)(1.0 / sqrt(var + 1e-5));
        float sc    = gamma[c] * rstd;
        scale[c]    = sc;
        shift[c]    = beta[c] - (float)mean * sc;
    }
}

__global__ void apply_bn_relu6(const float* __restrict__ pre,
                               float* __restrict__ out,
                               const float* __restrict__ scale,
                               const float* __restrict__ shift,
                               int total, int HoWo, int Cout)
{
    int i = blockIdx.x * blockDim.x + threadIdx.x;
    if (i < total) {
        int c = (i / HoWo) % Cout;
        out[i] = act6(pre[i], scale[c], shift[c]);
    }
}

extern "C" void kernel_launch(void* const* d_in, const int* in_sizes, int n_in,
                              void* d_out, int out_size)
{
    (void)in_sizes; (void)n_in; (void)out_size;
    const float* x = (const float*)d_in[0];
    const float* W[6]; const float* G[6]; const float* B[6];
    for (int i = 0; i < 6; i++) {
        W[i] = (const float*)d_in[1 + 3 * i];
        G[i] = (const float*)d_in[2 + 3 * i];
        B[i] = (const float*)d_in[3 + 3 * i];
    }

    float *patch, *bufA, *bufB, *wT, *scl, *shf;
    double *sum, *sq;
    cudaGetSymbolAddress((void**)&patch, g_patch);
    cudaGetSymbolAddress((void**)&bufA,  g_bufA);
    cudaGetSymbolAddress((void**)&bufB,  g_bufB);
    cudaGetSymbolAddress((void**)&wT,    g_wT);
    cudaGetSymbolAddress((void**)&scl,   g_scale);
    cudaGetSymbolAddress((void**)&shf,   g_shift);
    cudaGetSymbolAddress((void**)&sum,   g_sum);
    cudaGetSymbolAddress((void**)&sq,    g_sumsq);

    float  *SC[6], *SH[6];
    double *SU[6], *SQ[6];
    for (int i = 0; i < 6; i++) {
        SC[i] = scl + i * 512; SH[i] = shf + i * 512;
        SU[i] = sum + i * 512; SQ[i] = sq  + i * 512;
    }

    zero_stats_kernel<<<12, 256>>>();

    // ---------------- L1: 1x1 512->256, 38x38 (no input act) ----------------
    {
        const int M = 23104, M_pad = 23168, K = 512, Cout = 256, HW = 1444;
        t1x1_kernel<<<dim3((M + 255) / 256, K), 256>>>(x, patch, nullptr, nullptr, 0, M, M_pad, HW, K);
        wtrans_kernel<<<dim3(K / 32, Cout / 32), dim3(32, 8)>>>(W[0], wT, K, Cout);
        adder_gemm<128, 64, 8, 8, 4><<<dim3(M_pad / 128, Cout / 64), 128>>>(
            patch, wT, bufA, SU[0], SQ[0], M, M_pad, K, Cout, HW);
        finalize_bn<<<1, 256>>>(SU[0], SQ[0], G[0], B[0], SC[0], SH[0], Cout, M);
    }
    // ---------------- L2: 3x3 256->512 s2 p1, 38x38 -> 19x19 ----------------
    {
        const int M = 5776, M_pad = 5888, K = 2304, Cout = 512, HoWo = 361;
        im2col3x3_kernel<<<dim3((M + 255) / 256, K), 256>>>(
            bufA, patch, SC[0], SH[0], M, M_pad, 256, 38, 38, 19, 19, 2, 1);
        wtrans_kernel<<<dim3(K / 32, Cout / 32), dim3(32, 8)>>>(W[1], wT, K, Cout);
        adder_gemm<128, 64, 8, 8, 4><<<dim3(M_pad / 128, Cout / 64), 128>>>(
            patch, wT, bufB, SU[1], SQ[1], M, M_pad, K, Cout, HoWo);
        finalize_bn<<<2, 256>>>(SU[1], SQ[1], G[1], B[1], SC[1], SH[1], Cout, M);
    }
    // ---------------- L3: 1x1 512->128, 19x19 ----------------
    {
        const int M = 5776, M_pad = 5824, K = 512, Cout = 128, HW = 361;
        t1x1_kernel<<<dim3((M + 255) / 256, K), 256>>>(bufB, patch, SC[1], SH[1], 1, M, M_pad, HW, K);
        wtrans_kernel<<<dim3(K / 32, Cout / 32), dim3(32, 8)>>>(W[2], wT, K, Cout);
        adder_gemm<64, 64, 4, 8, 5><<<dim3(M_pad / 64, Cout / 64), 128>>>(
            patch, wT, bufA, SU[2], SQ[2], M, M_pad, K, Cout, HW);
        finalize_bn<<<1, 128>>>(SU[2], SQ[2], G[2], B[2], SC[2], SH[2], Cout, M);
    }
    // ---------------- L4: 3x3 128->256 s2 p1, 19x19 -> 10x10 ----------------
    {
        const int M = 1600, M_pad = 1600, K = 1152, Cout = 256, HoWo = 100;
        im2col3x3_kernel<<<dim3((M + 255) / 256, K), 256>>>(
            bufA, patch, SC[2], SH[2], M, M_pad, 128, 19, 19, 10, 10, 2, 1);
        wtrans_kernel<<<dim3(K / 32, Cout / 32), dim3(32, 8)>>>(W[3], wT, K, Cout);
        adder_gemm<64, 64, 4, 8, 5><<<dim3(M_pad / 64, Cout / 64), 128>>>(
            patch, wT, bufB, SU[3], SQ[3], M, M_pad, K, Cout, HoWo);
        finalize_bn<<<1, 256>>>(SU[3], SQ[3], G[3], B[3], SC[3], SH[3], Cout, M);
    }
    // ---------------- L5: 1x1 256->128, 10x10 ----------------
    {
        const int M = 1600, M_pad = 1600, K = 256, Cout = 128, HW = 100;
        t1x1_kernel<<<dim3((M + 255) / 256, K), 256>>>(bufB, patch, SC[3], SH[3], 1, M, M_pad, HW, K);
        wtrans_kernel<<<dim3(K / 32, Cout / 32), dim3(32, 8)>>>(W[4], wT, K, Cout);
        adder_gemm<64, 64, 4, 8, 5><<<dim3(M_pad / 64, Cout / 64), 128>>>(
            patch, wT, bufA, SU[4], SQ[4], M, M_pad, K, Cout, HW);
        finalize_bn<<<1, 128>>>(SU[4], SQ[4], G[4], B[4], SC[4], SH[4], Cout, M);
    }
    // ---------------- L6: 3x3 128->256 s2 p0, 10x10 -> 4x4 ----------------
    {
        const int M = 256, M_pad = 256, K = 1152, Cout = 256, HoWo = 16;
        im2col3x3_kernel<<<dim3(1, K), 256>>>(
            bufA, patch, SC[4], SH[4], M, M_pad, 128, 10, 10, 4, 4, 2, 0);
        wtrans_kernel<<<dim3(K / 32, Cout / 32), dim3(32, 8)>>>(W[5], wT, K, Cout);
        adder_gemm<64, 64, 4, 8, 5><<<dim3(M_pad / 64, Cout / 64), 128>>>(
            patch, wT, bufB, SU[5], SQ[5], M, M_pad, K, Cout, HoWo);
        finalize_bn<<<1, 256>>>(SU[5], SQ[5], G[5], B[5], SC[5], SH[5], Cout, M);
    }

    // Final BN + ReLU6 -> d_out  [16, 256, 4, 4]
    int total = 16 * 256 * 4 * 4;
    apply_bn_relu6<<<(total + 255) / 256, 256>>>(bufB, (float*)d_out, SC[5], SH[5],
                                                 total, 16, 256);
}

// round 7
// speedup vs baseline: 2.2336x; 1.1685x over previous
#include <cuda_runtime.h>

typedef unsigned long long u64;
#define ABS2_MASK 0x7FFFFFFF7FFFFFFFull

// Packed fp32x2 add (sm_103a): one fma-pipe instruction, 2 FP32 adds per lane.
__device__ __forceinline__ u64 addx2(u64 a, u64 b) {
    u64 d;
    asm("add.rn.f32x2 %0, %1, %2;" : "=l"(d) : "l"(a), "l"(b));
    return d;
}

__device__ __forceinline__ void cp_async16(unsigned smem_addr, const void* gptr) {
    asm volatile("cp.async.cg.shared.global [%0], [%1], 16;" :: "r"(smem_addr), "l"(gptr));
}
__device__ __forceinline__ void cp_commit() {
    asm volatile("cp.async.commit_group;");
}
template<int N>
__device__ __forceinline__ void cp_wait() {
    asm volatile("cp.async.wait_group %0;" :: "n"(N));
}

// ---------------- scratch (device globals; no runtime allocation) ----------
__device__ float  g_patch[13565952];            // [K][M_pad] patches (max 54.3 MB)
__device__ float  g_bufA[16 * 256 * 38 * 38];   // act ping (pre-BN), 23.7 MB
__device__ float  g_bufB[16 * 512 * 19 * 19];   // act pong, 11.8 MB
__device__ float  g_wT[2304 * 1024];            // negated, transposed, DUPLICATED weights
__device__ double g_sum[6][512];
__device__ double g_sumsq[6][512];
__device__ float  g_scale[6][512];
__device__ float  g_shift[6][512];

__global__ void zero_stats_kernel() {
    int i = blockIdx.x * blockDim.x + threadIdx.x;
    if (i < 6 * 512) {
        (&g_sum[0][0])[i]   = 0.0;
        (&g_sumsq[0][0])[i] = 0.0;
    }
}

__device__ __forceinline__ float act6(float v, float sc, float sh) {
    return fminf(fmaxf(fmaf(v, sc, sh), 0.f), 6.f);
}

// ---- 1x1 layers: NCHW -> [k][M_pad] transpose with BN+ReLU6 fold -----------
__global__ void t1x1_kernel(const float* __restrict__ src, float* __restrict__ P,
                            const float* __restrict__ scale,
                            const float* __restrict__ shift, int do_act,
                            int M, int M_pad, int HW, int Cin)
{
    int k = blockIdx.y;
    int m = blockIdx.x * blockDim.x + threadIdx.x;
    if (m >= M) return;
    int n = m / HW, s = m - n * HW;
    float v = src[(size_t)(n * Cin + k) * HW + s];
    if (do_act) v = act6(v, scale[k], shift[k]);
    P[(size_t)k * M_pad + m] = v;
}

// ---- 3x3 layers: im2col with BN+ReLU6 fold; OOB (padding) -> 0 ------------
__global__ void im2col3x3_kernel(const float* __restrict__ src, float* __restrict__ P,
                                 const float* __restrict__ scale,
                                 const float* __restrict__ shift,
                                 int M, int M_pad, int Cin, int H, int W,
                                 int Ho, int Wo, int stride, int pad)
{
    int k = blockIdx.y;
    int m = blockIdx.x * blockDim.x + threadIdx.x;
    if (m >= M) return;
    int c  = k / 9;
    int r  = k - 9 * c;
    int ky = r / 3;
    int kx = r - 3 * ky;
    int HoWo = Ho * Wo;
    int n  = m / HoWo, s  = m - n * HoWo;
    int oy = s / Wo,   ox = s - oy * Wo;
    int iy = oy * stride - pad + ky;
    int ix = ox * stride - pad + kx;
    float v = 0.f;
    if (iy >= 0 && iy < H && ix >= 0 && ix < W) {
        v = act6(src[((size_t)(n * Cin + c) * H + iy) * W + ix], scale[c], shift[c]);
    }
    P[(size_t)k * M_pad + m] = v;
}

// ---- weights: negate + transpose + DUPLICATE to [k][2*Cout] ---------------
__global__ void wtrans_kernel(const float* __restrict__ w, float* __restrict__ wT,
                              int K, int Cout)
{
    __shared__ float t[32][33];
    int bk  = blockIdx.x * 32;
    int bco = blockIdx.y * 32;
    int tx  = threadIdx.x, ty = threadIdx.y;   // (32, 8)
#pragma unroll
    for (int i = 0; i < 4; i++) {
        int co = bco + ty + i * 8;
        t[ty + i * 8][tx] = -w[(size_t)co * K + bk + tx];
    }
    __syncthreads();
#pragma unroll
    for (int i = 0; i < 4; i++) {
        int k = bk + ty + i * 8;
        float v = t[tx][ty + i * 8];
        *reinterpret_cast<float2*>(&wT[(size_t)k * 2 * Cout + 2 * (bco + tx)]) =
            make_float2(v, v);
    }
}

// ---------------------------------------------------------------------------
// Adder GEMM:  pre[m, co] = -sum_k |P[k,m] - W[co,k]|
// P: [K][M_pad]. Wd: [K][2*Cout] negated duplicated weights.
// Small tiles (64x32), 6 blocks/SM: fine-grained scheduling + latency hiding.
// cp.async double-buffered; per-channel stats fused into epilogue.
// ---------------------------------------------------------------------------
template<int BM, int BN, int TM, int TN, int MAXB>
__global__ __launch_bounds__(128, MAXB)
void adder_gemm(const float* __restrict__ P, const float* __restrict__ Wd,
                float* __restrict__ out,
                double* __restrict__ sum_g, double* __restrict__ sumsq_g,
                int M, int M_pad, int K, int Cout, int HoWo)
{
    constexpr int BK = 16;
    constexpr int NT = 128;
    static_assert(BM / TM == 16 && BN / TN == 8, "thread layout");
    __shared__ float sP[2][BK][BM];
    __shared__ float sW[2][BK][2 * BN];

    const int tid = threadIdx.x;
    const int m0  = blockIdx.x * BM;
    const int n0  = blockIdx.y * BN;
    const int txm = tid & 15;
    const int ty  = tid >> 4;
    const int tn0 = ty * TN;

    u64 acc[TM / 2][TN];
#pragma unroll
    for (int i = 0; i < TM / 2; i++)
#pragma unroll
        for (int j = 0; j < TN; j++) acc[i][j] = 0ull;

    const float* gP = P  + m0;
    const float* gW = Wd + 2 * n0;
    const int nTiles = K / BK;

    constexpr int PR = (BK * BM / 4) / NT;
    constexpr int WR = (BK * 2 * BN / 4) / NT;

    auto issue_tile = [&](int t, int buf) {
        const float* bP = gP + (size_t)t * BK * M_pad;
        const float* bW = gW + (size_t)t * BK * 2 * Cout;
#pragma unroll
        for (int r = 0; r < PR; r++) {
            int idx = r * NT + tid;
            int lk  = idx / (BM / 4);
            int c4  = idx - lk * (BM / 4);
            cp_async16((unsigned)__cvta_generic_to_shared(&sP[buf][lk][c4 * 4]),
                       bP + (size_t)lk * M_pad + c4 * 4);
        }
#pragma unroll
        for (int r = 0; r < WR; r++) {
            int idx = r * NT + tid;
            int lk  = idx / (2 * BN / 4);
            int c4  = idx - lk * (2 * BN / 4);
            cp_async16((unsigned)__cvta_generic_to_shared(&sW[buf][lk][c4 * 4]),
                       bW + (size_t)lk * 2 * Cout + c4 * 4);
        }
        cp_commit();
    };

    issue_tile(0, 0);

    for (int t = 0; t < nTiles; t++) {
        int buf = t & 1;
        if (t + 1 < nTiles) {
            issue_tile(t + 1, buf ^ 1);
            cp_wait<1>();
        } else {
            cp_wait<0>();
        }
        __syncthreads();

#pragma unroll
        for (int kk = 0; kk < BK; kk++) {
            // P chunk: one LDS.128 per thread; 8-lane phases hit 8 consecutive
            // 16B chunks -> conflict-free.
            u64 p2[TM / 2];
#pragma unroll
            for (int i = 0; i < TM / 4; i++) {
                ulonglong2 v = *reinterpret_cast<const ulonglong2*>(&sP[buf][kk][txm * 4 + 8 * i]);
                p2[2 * i]     = v.x;
                p2[2 * i + 1] = v.y;
            }
            // W pairs: 8-lane phases share ty -> broadcast, conflict-free.
            u64 w2[TN];
#pragma unroll
            for (int j = 0; j < TN / 2; j++) {
                ulonglong2 v = *reinterpret_cast<const ulonglong2*>(&sW[buf][kk][2 * tn0 + 4 * j]);
                w2[2 * j]     = v.x;
                w2[2 * j + 1] = v.y;
            }
#pragma unroll
            for (int i = 0; i < TM / 2; i++)
#pragma unroll
                for (int j = 0; j < TN; j++) {
                    u64 d = addx2(p2[i], w2[j]) & ABS2_MASK;
                    acc[i][j] = addx2(acc[i][j], d);
                }
        }
        __syncthreads();
    }

    // ---- writeback (-acc) + per-channel stats ----
    // acc[i][j] covers m = m0 + txm*4 + 2*i + {0,1}   (TM=4 path)
    float s_sum[TN], s_sq[TN];
#pragma unroll
    for (int j = 0; j < TN; j++) { s_sum[j] = 0.f; s_sq[j] = 0.f; }

#pragma unroll
    for (int i = 0; i < TM / 2; i++) {
        int mA = m0 + (i >> 1) * 8 + txm * 4 + (i & 1) * 2;   // general for TM=4/8 chunks of 8
        int mB = mA + 1;
        bool okA = mA < M, okB = mB < M;
        int nA = 0, sA = 0, nB = 0, sB = 0;
        if (okA) { nA = mA / HoWo; sA = mA - nA * HoWo; }
        if (okB) { nB = mB / HoWo; sB = mB - nB * HoWo; }
#pragma unroll
        for (int j = 0; j < TN; j++) {
            float lo = __uint_as_float((unsigned int)(acc[i][j] & 0xFFFFFFFFull));
            float hi = __uint_as_float((unsigned int)(acc[i][j] >> 32));
            float vA = -lo, vB = -hi;
            int c = n0 + tn0 + j;
            if (okA) {
                out[(size_t)(nA * Cout + c) * HoWo + sA] = vA;
                s_sum[j] += vA; s_sq[j] += vA * vA;
            }
            if (okB) {
                out[(size_t)(nB * Cout + c) * HoWo + sB] = vB;
                s_sum[j] += vB; s_sq[j] += vB * vB;
            }
        }
    }
#pragma unroll
    for (int j = 0; j < TN; j++) {
        float a = s_sum[j], b = s_sq[j];
#pragma unroll
        for (int o = 1; o < 16; o <<= 1) {
            a += __shfl_xor_sync(0xffffffffu, a, o);
            b += __shfl_xor_sync(0xffffffffu, b, o);
        }
        if (txm == 0) {
            int c = n0 + tn0 + j;
            atomicAdd(&sum_g[c],   (double)a);
            atomicAdd(&sumsq_g[c], (double)b);
        }
    }
}

__global__ void finalize_bn(const double* __restrict__ sum_g,
                            const double* __restrict__ sumsq_g,
                            const float* __restrict__ gamma,
                            const float* __restrict__ beta,
                            float* __restrict__ scale,
                            float* __restrict__ shift,
                            int Cout, int cnt)
{
    int c = blockIdx.x * blockDim.x + threadIdx.x;
    if (c < Cout) {
        double mean = sum_g[c] / cnt;
        double var  = sumsq_g[c] / cnt - mean * mean;
        float rstd  = (float)(1.0 / sqrt(var + 1e-5));
        float sc    = gamma[c] * rstd;
        scale[c]    = sc;
        shift[c]    = beta[c] - (float)mean * sc;
    }
}

__global__ void apply_bn_relu6(const float* __restrict__ pre,
                               float* __restrict__ out,
                               const float* __restrict__ scale,
                               const float* __restrict__ shift,
                               int total, int HoWo, int Cout)
{
    int i = blockIdx.x * blockDim.x + threadIdx.x;
    if (i < total) {
        int c = (i / HoWo) % Cout;
        out[i] = act6(pre[i], scale[c], shift[c]);
    }
}

extern "C" void kernel_launch(void* const* d_in, const int* in_sizes, int n_in,
                              void* d_out, int out_size)
{
    (void)in_sizes; (void)n_in; (void)out_size;
    const float* x = (const float*)d_in[0];
    const float* W[6]; const float* G[6]; const float* B[6];
    for (int i = 0; i < 6; i++) {
        W[i] = (const float*)d_in[1 + 3 * i];
        G[i] = (const float*)d_in[2 + 3 * i];
        B[i] = (const float*)d_in[3 + 3 * i];
    }

    float *patch, *bufA, *bufB, *wT, *scl, *shf;
    double *sum, *sq;
    cudaGetSymbolAddress((void**)&patch, g_patch);
    cudaGetSymbolAddress((void**)&bufA,  g_bufA);
    cudaGetSymbolAddress((void**)&bufB,  g_bufB);
    cudaGetSymbolAddress((void**)&wT,    g_wT);
    cudaGetSymbolAddress((void**)&scl,   g_scale);
    cudaGetSymbolAddress((void**)&shf,   g_shift);
    cudaGetSymbolAddress((void**)&sum,   g_sum);
    cudaGetSymbolAddress((void**)&sq,    g_sumsq);

    float  *SC[6], *SH[6];
    double *SU[6], *SQ[6];
    for (int i = 0; i < 6; i++) {
        SC[i] = scl + i * 512; SH[i] = shf + i * 512;
        SU[i] = sum + i * 512; SQ[i] = sq  + i * 512;
    }

    zero_stats_kernel<<<12, 256>>>();

    // ---------------- L1: 1x1 512->256, 38x38 (no input act) ----------------
    {
        const int M = 23104, M_pad = 23104, K = 512, Cout = 256, HW = 1444;
        t1x1_kernel<<<dim3((M + 255) / 256, K), 256>>>(x, patch, nullptr, nullptr, 0, M, M_pad, HW, K);
        wtrans_kernel<<<dim3(K / 32, Cout / 32), dim3(32, 8)>>>(W[0], wT, K, Cout);
        adder_gemm<64, 32, 4, 4, 6><<<dim3(M_pad / 64, Cout / 32), 128>>>(
            patch, wT, bufA, SU[0], SQ[0], M, M_pad, K, Cout, HW);
        finalize_bn<<<1, 256>>>(SU[0], SQ[0], G[0], B[0], SC[0], SH[0], Cout, M);
    }
    // ---------------- L2: 3x3 256->512 s2 p1, 38x38 -> 19x19 ----------------
    {
        const int M = 5776, M_pad = 5824, K = 2304, Cout = 512, HoWo = 361;
        im2col3x3_kernel<<<dim3((M + 255) / 256, K), 256>>>(
            bufA, patch, SC[0], SH[0], M, M_pad, 256, 38, 38, 19, 19, 2, 1);
        wtrans_kernel<<<dim3(K / 32, Cout / 32), dim3(32, 8)>>>(W[1], wT, K, Cout);
        adder_gemm<64, 32, 4, 4, 6><<<dim3(M_pad / 64, Cout / 32), 128>>>(
            patch, wT, bufB, SU[1], SQ[1], M, M_pad, K, Cout, HoWo);
        finalize_bn<<<2, 256>>>(SU[1], SQ[1], G[1], B[1], SC[1], SH[1], Cout, M);
    }
    // ---------------- L3: 1x1 512->128, 19x19 ----------------
    {
        const int M = 5776, M_pad = 5824, K = 512, Cout = 128, HW = 361;
        t1x1_kernel<<<dim3((M + 255) / 256, K), 256>>>(bufB, patch, SC[1], SH[1], 1, M, M_pad, HW, K);
        wtrans_kernel<<<dim3(K / 32, Cout / 32), dim3(32, 8)>>>(W[2], wT, K, Cout);
        adder_gemm<64, 32, 4, 4, 6><<<dim3(M_pad / 64, Cout / 32), 128>>>(
            patch, wT, bufA, SU[2], SQ[2], M, M_pad, K, Cout, HW);
        finalize_bn<<<1, 128>>>(SU[2], SQ[2], G[2], B[2], SC[2], SH[2], Cout, M);
    }
    // ---------------- L4: 3x3 128->256 s2 p1, 19x19 -> 10x10 ----------------
    {
        const int M = 1600, M_pad = 1600, K = 1152, Cout = 256, HoWo = 100;
        im2col3x3_kernel<<<dim3((M + 255) / 256, K), 256>>>(
            bufA, patch, SC[2], SH[2], M, M_pad, 128, 19, 19, 10, 10, 2, 1);
        wtrans_kernel<<<dim3(K / 32, Cout / 32), dim3(32, 8)>>>(W[3], wT, K, Cout);
        adder_gemm<64, 32, 4, 4, 6><<<dim3(M_pad / 64, Cout / 32), 128>>>(
            patch, wT, bufB, SU[3], SQ[3], M, M_pad, K, Cout, HoWo);
        finalize_bn<<<1, 256>>>(SU[3], SQ[3], G[3], B[3], SC[3], SH[3], Cout, M);
    }
    // ---------------- L5: 1x1 256->128, 10x10 ----------------
    {
        const int M = 1600, M_pad = 1600, K = 256, Cout = 128, HW = 100;
        t1x1_kernel<<<dim3((M + 255) / 256, K), 256>>>(bufB, patch, SC[3], SH[3], 1, M, M_pad, HW, K);
        wtrans_kernel<<<dim3(K / 32, Cout / 32), dim3(32, 8)>>>(W[4], wT, K, Cout);
        adder_gemm<64, 32, 4, 4, 6><<<dim3(M_pad / 64, Cout / 32), 128>>>(
            patch, wT, bufA, SU[4], SQ[4], M, M_pad, K, Cout, HW);
        finalize_bn<<<1, 128>>>(SU[4], SQ[4], G[4], B[4], SC[4], SH[4], Cout, M);
    }
    // ---------------- L6: 3x3 128->256 s2 p0, 10x10 -> 4x4 ----------------
    {
        const int M = 256, M_pad = 256, K = 1152, Cout = 256, HoWo = 16;
        im2col3x3_kernel<<<dim3(1, K), 256>>>(
            bufA, patch, SC[4], SH[4], M, M_pad, 128, 10, 10, 4, 4, 2, 0);
        wtrans_kernel<<<dim3(K / 32, Cout / 32), dim3(32, 8)>>>(W[5], wT, K, Cout);
        adder_gemm<64, 32, 4, 4, 6><<<dim3(M_pad / 64, Cout / 32), 128>>>(
            patch, wT, bufB, SU[5], SQ[5], M, M_pad, K, Cout, HoWo);
        finalize_bn<<<1, 256>>>(SU[5], SQ[5], G[5], B[5], SC[5], SH[5], Cout, M);
    }

    // Final BN + ReLU6 -> d_out  [16, 256, 4, 4]
    int total = 16 * 256 * 4 * 4;
    apply_bn_relu6<<<(total + 255) / 256, 256>>>(bufB, (float*)d_out, SC[5], SH[5],
                                                 total, 16, 256);
}

// round 8
// speedup vs baseline: 2.4048x; 1.0766x over previous
#include <cuda_runtime.h>

typedef unsigned long long u64;

// acc += 2.0 * {lo, hi}  (packed f32x2 FMA, fma pipe; ptxas packs lo/hi into a reg pair)
__device__ __forceinline__ void fma2acc(u64& acc, float lo, float hi) {
    asm("{\n\t.reg .b64 t;\n\tmov.b64 t, {%1, %2};\n\tfma.rn.f32x2 %0, t, %3, %0;\n\t}"
        : "+l"(acc) : "f"(lo), "f"(hi), "l"(0x4000000040000000ull));
}

__device__ __forceinline__ void cp_async16(unsigned smem_addr, const void* gptr) {
    asm volatile("cp.async.cg.shared.global [%0], [%1], 16;" :: "r"(smem_addr), "l"(gptr));
}
__device__ __forceinline__ void cp_commit() {
    asm volatile("cp.async.commit_group;");
}
template<int N>
__device__ __forceinline__ void cp_wait() {
    asm volatile("cp.async.wait_group %0;" :: "n"(N));
}

// ---------------- scratch (device globals; no runtime allocation) ----------
__device__ float  g_patch[13565952];            // [K][M_pad] patches (max 54.3 MB)
__device__ float  g_bufA[16 * 256 * 38 * 38];   // act ping (pre-BN), 23.7 MB
__device__ float  g_bufB[16 * 512 * 19 * 19];   // act pong, 11.8 MB
__device__ float  g_wT[2304 * 512];             // transposed weights [k][Cout]
__device__ float  g_sumP[23168];                // Sp[m] = sum_k P[k][m]
__device__ float  g_sumW[512];                  // Sw[co] = sum_k w[co][k]
__device__ double g_sum[6][512];
__device__ double g_sumsq[6][512];
__device__ float  g_scale[6][512];
__device__ float  g_shift[6][512];

__global__ void zero_stats_kernel() {
    int i = blockIdx.x * blockDim.x + threadIdx.x;
    if (i < 6 * 512) {
        (&g_sum[0][0])[i]   = 0.0;
        (&g_sumsq[0][0])[i] = 0.0;
    }
}

__global__ void zero_sumP_kernel(float* Sp, int M_pad) {
    int i = blockIdx.x * blockDim.x + threadIdx.x;
    if (i < M_pad) Sp[i] = 0.f;
}

__device__ __forceinline__ float act6(float v, float sc, float sh) {
    return fminf(fmaxf(fmaf(v, sc, sh), 0.f), 6.f);
}

// ---- 1x1 layers: NCHW -> [k][M_pad] transpose with BN+ReLU6 fold -----------
__global__ void t1x1_kernel(const float* __restrict__ src, float* __restrict__ P,
                            const float* __restrict__ scale,
                            const float* __restrict__ shift, int do_act,
                            int M, int M_pad, int HW, int Cin)
{
    int k = blockIdx.y;
    int m = blockIdx.x * blockDim.x + threadIdx.x;
    if (m >= M) return;
    int n = m / HW, s = m - n * HW;
    float v = src[(size_t)(n * Cin + k) * HW + s];
    if (do_act) v = act6(v, scale[k], shift[k]);
    P[(size_t)k * M_pad + m] = v;
}

// ---- 3x3 layers: im2col with BN+ReLU6 fold; OOB (padding) -> 0 ------------
__global__ void im2col3x3_kernel(const float* __restrict__ src, float* __restrict__ P,
                                 const float* __restrict__ scale,
                                 const float* __restrict__ shift,
                                 int M, int M_pad, int Cin, int H, int W,
                                 int Ho, int Wo, int stride, int pad)
{
    int k = blockIdx.y;
    int m = blockIdx.x * blockDim.x + threadIdx.x;
    if (m >= M) return;
    int c  = k / 9;
    int r  = k - 9 * c;
    int ky = r / 3;
    int kx = r - 3 * ky;
    int HoWo = Ho * Wo;
    int n  = m / HoWo, s  = m - n * HoWo;
    int oy = s / Wo,   ox = s - oy * Wo;
    int iy = oy * stride - pad + ky;
    int ix = ox * stride - pad + kx;
    float v = 0.f;
    if (iy >= 0 && iy < H && ix >= 0 && ix < W) {
        v = act6(src[((size_t)(n * Cin + c) * H + iy) * W + ix], scale[c], shift[c]);
    }
    P[(size_t)k * M_pad + m] = v;
}

// ---- Sp[m] = sum_k P[k][m], chunked over K with float atomics -------------
__global__ void sumP_kernel(const float* __restrict__ P, float* __restrict__ Sp,
                            int M, int M_pad)
{
    int m  = blockIdx.x * blockDim.x + threadIdx.x;
    int k0 = blockIdx.y * 128;
    if (m >= M) return;
    float s = 0.f;
    const float* p = P + (size_t)k0 * M_pad + m;
#pragma unroll 8
    for (int k = 0; k < 128; k++) { s += *p; p += M_pad; }
    atomicAdd(&Sp[m], s);
}

// ---- Sw[co] = sum_k w[co][k]  (one warp per co) ----------------------------
__global__ void sumW_kernel(const float* __restrict__ w, float* __restrict__ Sw, int K)
{
    int co = blockIdx.x, lane = threadIdx.x;
    float s = 0.f;
    for (int k = lane; k < K; k += 32) s += w[(size_t)co * K + k];
#pragma unroll
    for (int o = 16; o > 0; o >>= 1) s += __shfl_xor_sync(0xffffffffu, s, o);
    if (lane == 0) Sw[co] = s;
}

// ---- weights: plain transpose to [k][Cout] ---------------------------------
__global__ void wtrans_kernel(const float* __restrict__ w, float* __restrict__ wT,
                              int K, int Cout)
{
    __shared__ float t[32][33];
    int bk  = blockIdx.x * 32;
    int bco = blockIdx.y * 32;
    int tx  = threadIdx.x, ty = threadIdx.y;   // (32, 8)
#pragma unroll
    for (int i = 0; i < 4; i++) {
        int co = bco + ty + i * 8;
        t[ty + i * 8][tx] = w[(size_t)co * K + bk + tx];
    }
    __syncthreads();
#pragma unroll
    for (int i = 0; i < 4; i++) {
        int k = bk + ty + i * 8;
        wT[(size_t)k * Cout + bco + tx] = t[tx][ty + i * 8];
    }
}

// ---------------------------------------------------------------------------
// Adder GEMM via min-identity:
//   pre[m,co] = -sum_k |P[k,m]-W[co,k]| = 2*sum_k min(P,W) - Sp[m] - Sw[co]
// Inner loop: FMNMX (alu) + packed fma x2.0 (fma) only. cp.async double-buffer.
// ---------------------------------------------------------------------------
template<int BM, int BN, int TM, int TN, int MAXB>
__global__ __launch_bounds__(128, MAXB)
void adder_gemm(const float* __restrict__ P, const float* __restrict__ Wt,
                const float* __restrict__ Sp, const float* __restrict__ Sw,
                float* __restrict__ out,
                double* __restrict__ sum_g, double* __restrict__ sumsq_g,
                int M, int M_pad, int K, int Cout, int HoWo)
{
    constexpr int BK = 16;
    constexpr int NT = 128;
    static_assert(BM == 64 && BN == 32 && TM == 4 && TN == 4, "fixed config");
    __shared__ float sP[2][BK][BM];
    __shared__ float sW[2][BK][BN];

    const int tid = threadIdx.x;
    const int m0  = blockIdx.x * BM;
    const int n0  = blockIdx.y * BN;
    const int txm = tid & 15;
    const int ty  = tid >> 4;
    const int tn0 = ty * TN;

    u64 acc[2][TN];
#pragma unroll
    for (int i = 0; i < 2; i++)
#pragma unroll
        for (int j = 0; j < TN; j++) acc[i][j] = 0ull;

    const float* gP = P  + m0;
    const float* gW = Wt + n0;
    const int nTiles = K / BK;

    auto issue_tile = [&](int t, int buf) {
        const float* bP = gP + (size_t)t * BK * M_pad;
        const float* bW = gW + (size_t)t * BK * Cout;
        // P tile: 256 16B-chunks, 2 per thread
#pragma unroll
        for (int r = 0; r < 2; r++) {
            int idx = r * NT + tid;
            int lk  = idx >> 4;            // / (BM/4)
            int c4  = idx & 15;
            cp_async16((unsigned)__cvta_generic_to_shared(&sP[buf][lk][c4 * 4]),
                       bP + (size_t)lk * M_pad + c4 * 4);
        }
        // W tile: 128 16B-chunks, 1 per thread
        {
            int lk = tid >> 3;             // / (BN/4)
            int c4 = tid & 7;
            cp_async16((unsigned)__cvta_generic_to_shared(&sW[buf][lk][c4 * 4]),
                       bW + (size_t)lk * Cout + c4 * 4);
        }
        cp_commit();
    };

    issue_tile(0, 0);

    for (int t = 0; t < nTiles; t++) {
        int buf = t & 1;
        if (t + 1 < nTiles) {
            issue_tile(t + 1, buf ^ 1);
            cp_wait<1>();
        } else {
            cp_wait<0>();
        }
        __syncthreads();

#pragma unroll
        for (int kk = 0; kk < BK; kk++) {
            // P: 8-lane phases hit 8 consecutive 16B chunks -> conflict-free.
            float4 p = *reinterpret_cast<const float4*>(&sP[buf][kk][txm * 4]);
            // W: 8-lane phases share ty -> broadcast.
            float4 w = *reinterpret_cast<const float4*>(&sW[buf][kk][tn0]);
            float wv[4] = {w.x, w.y, w.z, w.w};
#pragma unroll
            for (int j = 0; j < TN; j++) {
                fma2acc(acc[0][j], fminf(p.x, wv[j]), fminf(p.y, wv[j]));
                fma2acc(acc[1][j], fminf(p.z, wv[j]), fminf(p.w, wv[j]));
            }
        }
        __syncthreads();
    }

    // ---- epilogue: val = acc(=2*sum min) - Sp[m] - Sw[co]; fused BN stats --
    float4 spv = *reinterpret_cast<const float4*>(&Sp[m0 + txm * 4]);
    float4 swv = *reinterpret_cast<const float4*>(&Sw[n0 + tn0]);
    float spA[4] = {spv.x, spv.y, spv.z, spv.w};
    float swA[4] = {swv.x, swv.y, swv.z, swv.w};

    float s_sum[TN], s_sq[TN];
#pragma unroll
    for (int j = 0; j < TN; j++) { s_sum[j] = 0.f; s_sq[j] = 0.f; }

#pragma unroll
    for (int i = 0; i < 2; i++) {
        int mA = m0 + txm * 4 + 2 * i;
        int mB = mA + 1;
        bool okA = mA < M, okB = mB < M;
        int nA = 0, sA = 0, nB = 0, sB = 0;
        if (okA) { nA = mA / HoWo; sA = mA - nA * HoWo; }
        if (okB) { nB = mB / HoWo; sB = mB - nB * HoWo; }
#pragma unroll
        for (int j = 0; j < TN; j++) {
            float lo = __uint_as_float((unsigned int)(acc[i][j] & 0xFFFFFFFFull));
            float hi = __uint_as_float((unsigned int)(acc[i][j] >> 32));
            float vA = lo - spA[2 * i]     - swA[j];
            float vB = hi - spA[2 * i + 1] - swA[j];
            int c = n0 + tn0 + j;
            if (okA) {
                out[(size_t)(nA * Cout + c) * HoWo + sA] = vA;
                s_sum[j] += vA; s_sq[j] += vA * vA;
            }
            if (okB) {
                out[(size_t)(nB * Cout + c) * HoWo + sB] = vB;
                s_sum[j] += vB; s_sq[j] += vB * vB;
            }
        }
    }
#pragma unroll
    for (int j = 0; j < TN; j++) {
        float a = s_sum[j], b = s_sq[j];
#pragma unroll
        for (int o = 1; o < 16; o <<= 1) {
            a += __shfl_xor_sync(0xffffffffu, a, o);
            b += __shfl_xor_sync(0xffffffffu, b, o);
        }
        if (txm == 0) {
            int c = n0 + tn0 + j;
            atomicAdd(&sum_g[c],   (double)a);
            atomicAdd(&sumsq_g[c], (double)b);
        }
    }
}

__global__ void finalize_bn(const double* __restrict__ sum_g,
                            const double* __restrict__ sumsq_g,
                            const float* __restrict__ gamma,
                            const float* __restrict__ beta,
                            float* __restrict__ scale,
                            float* __restrict__ shift,
                            int Cout, int cnt)
{
    int c = blockIdx.x * blockDim.x + threadIdx.x;
    if (c < Cout) {
        double mean = sum_g[c] / cnt;
        double var  = sumsq_g[c] / cnt - mean * mean;
        float rstd  = (float)(1.0 / sqrt(var + 1e-5));
        float sc    = gamma[c] * rstd;
        scale[c]    = sc;
        shift[c]    = beta[c] - (float)mean * sc;
    }
}

__global__ void apply_bn_relu6(const float* __restrict__ pre,
                               float* __restrict__ out,
                               const float* __restrict__ scale,
                               const float* __restrict__ shift,
                               int total, int HoWo, int Cout)
{
    int i = blockIdx.x * blockDim.x + threadIdx.x;
    if (i < total) {
        int c = (i / HoWo) % Cout;
        out[i] = act6(pre[i], scale[c], shift[c]);
    }
}

struct Layer { int M, M_pad, K, Cout, HoWo; };

extern "C" void kernel_launch(void* const* d_in, const int* in_sizes, int n_in,
                              void* d_out, int out_size)
{
    (void)in_sizes; (void)n_in; (void)out_size;
    const float* x = (const float*)d_in[0];
    const float* W[6]; const float* G[6]; const float* B[6];
    for (int i = 0; i < 6; i++) {
        W[i] = (const float*)d_in[1 + 3 * i];
        G[i] = (const float*)d_in[2 + 3 * i];
        B[i] = (const float*)d_in[3 + 3 * i];
    }

    float *patch, *bufA, *bufB, *wT, *scl, *shf, *sp, *sw;
    double *sum, *sq;
    cudaGetSymbolAddress((void**)&patch, g_patch);
    cudaGetSymbolAddress((void**)&bufA,  g_bufA);
    cudaGetSymbolAddress((void**)&bufB,  g_bufB);
    cudaGetSymbolAddress((void**)&wT,    g_wT);
    cudaGetSymbolAddress((void**)&scl,   g_scale);
    cudaGetSymbolAddress((void**)&shf,   g_shift);
    cudaGetSymbolAddress((void**)&sp,    g_sumP);
    cudaGetSymbolAddress((void**)&sw,    g_sumW);
    cudaGetSymbolAddress((void**)&sum,   g_sum);
    cudaGetSymbolAddress((void**)&sq,    g_sumsq);

    float  *SC[6], *SH[6];
    double *SU[6], *SQ[6];
    for (int i = 0; i < 6; i++) {
        SC[i] = scl + i * 512; SH[i] = shf + i * 512;
        SU[i] = sum + i * 512; SQ[i] = sq  + i * 512;
    }

    zero_stats_kernel<<<12, 256>>>();

    const Layer L[6] = {
        {23104, 23104, 512,  256, 1444},  // L1: 1x1 512->256 @38x38
        {5776,  5824,  2304, 512, 361},   // L2: 3x3 256->512 s2p1 ->19x19
        {5776,  5824,  512,  128, 361},   // L3: 1x1 512->128 @19x19
        {1600,  1600,  1152, 256, 100},   // L4: 3x3 128->256 s2p1 ->10x10
        {1600,  1600,  256,  128, 100},   // L5: 1x1 256->128 @10x10
        {256,   256,   1152, 256, 16},    // L6: 3x3 128->256 s2p0 ->4x4
    };

    const float* srcs[6] = {x, bufA, bufB, bufA, bufB, bufA};
    float*       dsts[6] = {bufA, bufB, bufA, bufB, bufA, bufB};

    for (int li = 0; li < 6; li++) {
        const Layer& l = L[li];
        // prep: patches
        if (li == 0) {
            t1x1_kernel<<<dim3((l.M + 255) / 256, l.K), 256>>>(
                srcs[li], patch, nullptr, nullptr, 0, l.M, l.M_pad, l.HoWo, l.K);
        } else if (li == 2) {
            t1x1_kernel<<<dim3((l.M + 255) / 256, l.K), 256>>>(
                srcs[li], patch, SC[1], SH[1], 1, l.M, l.M_pad, l.HoWo, l.K);
        } else if (li == 4) {
            t1x1_kernel<<<dim3((l.M + 255) / 256, l.K), 256>>>(
                srcs[li], patch, SC[3], SH[3], 1, l.M, l.M_pad, l.HoWo, l.K);
        } else if (li == 1) {
            im2col3x3_kernel<<<dim3((l.M + 255) / 256, l.K), 256>>>(
                srcs[li], patch, SC[0], SH[0], l.M, l.M_pad, 256, 38, 38, 19, 19, 2, 1);
        } else if (li == 3) {
            im2col3x3_kernel<<<dim3((l.M + 255) / 256, l.K), 256>>>(
                srcs[li], patch, SC[2], SH[2], l.M, l.M_pad, 128, 19, 19, 10, 10, 2, 1);
        } else {
            im2col3x3_kernel<<<dim3((l.M + 255) / 256, l.K), 256>>>(
                srcs[li], patch, SC[4], SH[4], l.M, l.M_pad, 128, 10, 10, 4, 4, 2, 0);
        }
        // row/col sums
        zero_sumP_kernel<<<(l.M_pad + 255) / 256, 256>>>(sp, l.M_pad);
        sumP_kernel<<<dim3((l.M + 255) / 256, l.K / 128), 256>>>(patch, sp, l.M, l.M_pad);
        sumW_kernel<<<l.Cout, 32>>>(W[li], sw, l.K);
        // transpose weights
        wtrans_kernel<<<dim3(l.K / 32, l.Cout / 32), dim3(32, 8)>>>(W[li], wT, l.K, l.Cout);
        // GEMM + fused stats
        adder_gemm<64, 32, 4, 4, 8><<<dim3(l.M_pad / 64, l.Cout / 32), 128>>>(
            patch, wT, sp, sw, dsts[li], SU[li], SQ[li], l.M, l.M_pad, l.K, l.Cout, l.HoWo);
        finalize_bn<<<(l.Cout + 127) / 128, 128>>>(SU[li], SQ[li], G[li], B[li],
                                                   SC[li], SH[li], l.Cout, l.M);
    }

    // Final BN + ReLU6 -> d_out  [16, 256, 4, 4]
    int total = 16 * 256 * 4 * 4;
    apply_bn_relu6<<<(total + 255) / 256, 256>>>(bufB, (float*)d_out, SC[5], SH[5],
                                                 total, 16, 256);
}

// round 10
// speedup vs baseline: 2.7321x; 1.1361x over previous
#include <cuda_runtime.h>

typedef unsigned long long u64;

// acc += 2.0 * {lo, hi}  (packed f32x2 FMA on the fma pipe)
__device__ __forceinline__ void fma2acc(u64& acc, float lo, float hi) {
    asm("{\n\t.reg .b64 t;\n\tmov.b64 t, {%1, %2};\n\tfma.rn.f32x2 %0, t, %3, %0;\n\t}"
        : "+l"(acc) : "f"(lo), "f"(hi), "l"(0x4000000040000000ull));
}
// acc += {lo, hi}  (packed f32x2 add on the fma pipe)
__device__ __forceinline__ void add2acc(u64& acc, float lo, float hi) {
    asm("{\n\t.reg .b64 t;\n\tmov.b64 t, {%1, %2};\n\tadd.rn.f32x2 %0, %0, t;\n\t}"
        : "+l"(acc) : "f"(lo), "f"(hi));
}

__device__ __forceinline__ void cp_async16(unsigned smem_addr, const void* gptr) {
    asm volatile("cp.async.cg.shared.global [%0], [%1], 16;" :: "r"(smem_addr), "l"(gptr));
}
__device__ __forceinline__ void cp_commit() {
    asm volatile("cp.async.commit_group;");
}
template<int N>
__device__ __forceinline__ void cp_wait() {
    asm volatile("cp.async.wait_group %0;" :: "n"(N));
}

// ---------------- scratch (device globals; no runtime allocation) ----------
__device__ float  g_patch[13565952];            // [K][M_pad] patches (max 54.3 MB)
__device__ float  g_bufA[16 * 256 * 38 * 38];   // act ping (pre-BN), 23.7 MB
__device__ float  g_bufB[16 * 512 * 19 * 19];   // act pong, 11.8 MB
__device__ float  g_wT[2304 * 512];             // transposed weights [k][Cout]
__device__ float  g_sumW[512];                  // Sw[co] = sum_k w[co][k]
__device__ double g_sum[6][512];
__device__ double g_sumsq[6][512];
__device__ float  g_scale[6][512];
__device__ float  g_shift[6][512];

__global__ void zero_stats_kernel() {
    int i = blockIdx.x * blockDim.x + threadIdx.x;
    if (i < 6 * 512) {
        (&g_sum[0][0])[i]   = 0.0;
        (&g_sumsq[0][0])[i] = 0.0;
    }
}

__device__ __forceinline__ float act6(float v, float sc, float sh) {
    return fminf(fmaxf(fmaf(v, sc, sh), 0.f), 6.f);
}

// ---- 1x1 layers: NCHW -> [k][M_pad] transpose with BN+ReLU6 fold -----------
__global__ void t1x1_kernel(const float* __restrict__ src, float* __restrict__ P,
                            const float* __restrict__ scale,
                            const float* __restrict__ shift, int do_act,
                            int M, int M_pad, int HW, int Cin)
{
    int k = blockIdx.y;
    int m = blockIdx.x * blockDim.x + threadIdx.x;
    if (m >= M) return;
    int n = m / HW, s = m - n * HW;
    float v = src[(size_t)(n * Cin + k) * HW + s];
    if (do_act) v = act6(v, scale[k], shift[k]);
    P[(size_t)k * M_pad + m] = v;
}

// ---- 3x3 layers: im2col with BN+ReLU6 fold; OOB (padding) -> 0 ------------
__global__ void im2col3x3_kernel(const float* __restrict__ src, float* __restrict__ P,
                                 const float* __restrict__ scale,
                                 const float* __restrict__ shift,
                                 int M, int M_pad, int Cin, int H, int W,
                                 int Ho, int Wo, int stride, int pad)
{
    int k = blockIdx.y;
    int m = blockIdx.x * blockDim.x + threadIdx.x;
    if (m >= M) return;
    int c  = k / 9;
    int r  = k - 9 * c;
    int ky = r / 3;
    int kx = r - 3 * ky;
    int HoWo = Ho * Wo;
    int n  = m / HoWo, s  = m - n * HoWo;
    int oy = s / Wo,   ox = s - oy * Wo;
    int iy = oy * stride - pad + ky;
    int ix = ox * stride - pad + kx;
    float v = 0.f;
    if (iy >= 0 && iy < H && ix >= 0 && ix < W) {
        v = act6(src[((size_t)(n * Cin + c) * H + iy) * W + ix], scale[c], shift[c]);
    }
    P[(size_t)k * M_pad + m] = v;
}

// ---- Sw[co] = sum_k w[co][k]  (one warp per co) ----------------------------
__global__ void sumW_kernel(const float* __restrict__ w, float* __restrict__ Sw, int K)
{
    int co = blockIdx.x, lane = threadIdx.x;
    float s = 0.f;
    for (int k = lane; k < K; k += 32) s += w[(size_t)co * K + k];
#pragma unroll
    for (int o = 16; o > 0; o >>= 1) s += __shfl_xor_sync(0xffffffffu, s, o);
    if (lane == 0) Sw[co] = s;
}

// ---- weights: plain transpose to [k][Cout] ---------------------------------
__global__ void wtrans_kernel(const float* __restrict__ w, float* __restrict__ wT,
                              int K, int Cout)
{
    __shared__ float t[32][33];
    int bk  = blockIdx.x * 32;
    int bco = blockIdx.y * 32;
    int tx  = threadIdx.x, ty = threadIdx.y;   // (32, 8)
#pragma unroll
    for (int i = 0; i < 4; i++) {
        int co = bco + ty + i * 8;
        t[ty + i * 8][tx] = w[(size_t)co * K + bk + tx];
    }
    __syncthreads();
#pragma unroll
    for (int i = 0; i < 4; i++) {
        int k = bk + ty + i * 8;
        wT[(size_t)k * Cout + bco + tx] = t[tx][ty + i * 8];
    }
}

// ---------------------------------------------------------------------------
// Adder GEMM via min-identity:
//   pre[m,co] = 2*sum_k min(P[k,m],W[co,k]) - Sp[m] - Sw[co]
// Sp[m] accumulated IN-LOOP on the fma pipe (each block spans full K).
// Inner loop: 16 FMNMX (alu, binding) + 10 f32x2 ops (fma) + 2 LDS per kk.
// BK=32, cp.async double-buffered.
// ---------------------------------------------------------------------------
__global__ __launch_bounds__(128, 7)
void adder_gemm(const float* __restrict__ P, const float* __restrict__ Wt,
                const float* __restrict__ Sw,
                float* __restrict__ out,
                double* __restrict__ sum_g, double* __restrict__ sumsq_g,
                int M, int M_pad, int K, int Cout, int HoWo)
{
    constexpr int BK = 32, BM = 64, BN = 32, TN = 4;
    constexpr int NT = 128;
    __shared__ float sP[2][BK][BM];
    __shared__ float sW[2][BK][BN];

    const int tid = threadIdx.x;
    const int m0  = blockIdx.x * BM;
    const int n0  = blockIdx.y * BN;
    const int txm = tid & 15;
    const int ty  = tid >> 4;
    const int tn0 = ty * TN;

    u64 acc[2][TN];
    u64 sp2[2] = {0ull, 0ull};
#pragma unroll
    for (int i = 0; i < 2; i++)
#pragma unroll
        for (int j = 0; j < TN; j++) acc[i][j] = 0ull;

    const float* gP = P  + m0;
    const float* gW = Wt + n0;
    const int nTiles = K / BK;

    auto issue_tile = [&](int t, int buf) {
        const float* bP = gP + (size_t)t * BK * M_pad;
        const float* bW = gW + (size_t)t * BK * Cout;
        // P tile: 512 16B chunks, 4 per thread
#pragma unroll
        for (int r = 0; r < 4; r++) {
            int idx = r * NT + tid;
            int lk  = idx >> 4;
            int c4  = idx & 15;
            cp_async16((unsigned)__cvta_generic_to_shared(&sP[buf][lk][c4 * 4]),
                       bP + (size_t)lk * M_pad + c4 * 4);
        }
        // W tile: 256 16B chunks, 2 per thread
#pragma unroll
        for (int r = 0; r < 2; r++) {
            int idx = r * NT + tid;
            int lk  = idx >> 3;
            int c4  = idx & 7;
            cp_async16((unsigned)__cvta_generic_to_shared(&sW[buf][lk][c4 * 4]),
                       bW + (size_t)lk * Cout + c4 * 4);
        }
        cp_commit();
    };

    issue_tile(0, 0);

    for (int t = 0; t < nTiles; t++) {
        int buf = t & 1;
        if (t + 1 < nTiles) {
            issue_tile(t + 1, buf ^ 1);
            cp_wait<1>();
        } else {
            cp_wait<0>();
        }
        __syncthreads();

#pragma unroll
        for (int kk = 0; kk < BK; kk++) {
            // P: 8-lane phases hit 8 consecutive 16B chunks -> conflict-free
            float4 p = *reinterpret_cast<const float4*>(&sP[buf][kk][txm * 4]);
            // W: 8-lane phases share ty -> broadcast
            float4 w = *reinterpret_cast<const float4*>(&sW[buf][kk][tn0]);
            float wv[4] = {w.x, w.y, w.z, w.w};
            // in-loop Sp accumulation (fma pipe)
            add2acc(sp2[0], p.x, p.y);
            add2acc(sp2[1], p.z, p.w);
#pragma unroll
            for (int j = 0; j < TN; j++) {
                fma2acc(acc[0][j], fminf(p.x, wv[j]), fminf(p.y, wv[j]));
                fma2acc(acc[1][j], fminf(p.z, wv[j]), fminf(p.w, wv[j]));
            }
        }
        __syncthreads();
    }

    // ---- epilogue: val = acc(=2*sum min) - Sp[m] - Sw[co]; fused BN stats --
    float4 swv = *reinterpret_cast<const float4*>(&Sw[n0 + tn0]);
    float swA[4] = {swv.x, swv.y, swv.z, swv.w};
    float spL[4];
    spL[0] = __uint_as_float((unsigned int)(sp2[0] & 0xFFFFFFFFull));
    spL[1] = __uint_as_float((unsigned int)(sp2[0] >> 32));
    spL[2] = __uint_as_float((unsigned int)(sp2[1] & 0xFFFFFFFFull));
    spL[3] = __uint_as_float((unsigned int)(sp2[1] >> 32));

    float s_sum[TN], s_sq[TN];
#pragma unroll
    for (int j = 0; j < TN; j++) { s_sum[j] = 0.f; s_sq[j] = 0.f; }

#pragma unroll
    for (int i = 0; i < 2; i++) {
        int mA = m0 + txm * 4 + 2 * i;
        int mB = mA + 1;
        bool okA = mA < M, okB = mB < M;
        int nA = 0, sA = 0, nB = 0, sB = 0;
        if (okA) { nA = mA / HoWo; sA = mA - nA * HoWo; }
        if (okB) { nB = mB / HoWo; sB = mB - nB * HoWo; }
#pragma unroll
        for (int j = 0; j < TN; j++) {
            float lo = __uint_as_float((unsigned int)(acc[i][j] & 0xFFFFFFFFull));
            float hi = __uint_as_float((unsigned int)(acc[i][j] >> 32));
            float vA = lo - spL[2 * i]     - swA[j];
            float vB = hi - spL[2 * i + 1] - swA[j];
            int c = n0 + tn0 + j;
            if (okA) {
                out[(size_t)(nA * Cout + c) * HoWo + sA] = vA;
                s_sum[j] += vA; s_sq[j] += vA * vA;
            }
            if (okB) {
                out[(size_t)(nB * Cout + c) * HoWo + sB] = vB;
                s_sum[j] += vB; s_sq[j] += vB * vB;
            }
        }
    }
#pragma unroll
    for (int j = 0; j < TN; j++) {
        float a = s_sum[j], b = s_sq[j];
#pragma unroll
        for (int o = 1; o < 16; o <<= 1) {
            a += __shfl_xor_sync(0xffffffffu, a, o);
            b += __shfl_xor_sync(0xffffffffu, b, o);
        }
        if (txm == 0) {
            int c = n0 + tn0 + j;
            atomicAdd(&sum_g[c],   (double)a);
            atomicAdd(&sumsq_g[c], (double)b);
        }
    }
}

__global__ void finalize_bn(const double* __restrict__ sum_g,
                            const double* __restrict__ sumsq_g,
                            const float* __restrict__ gamma,
                            const float* __restrict__ beta,
                            float* __restrict__ scale,
                            float* __restrict__ shift,
                            int Cout, int cnt)
{
    int c = blockIdx.x * blockDim.x + threadIdx.x;
    if (c < Cout) {
        double mean = sum_g[c] / cnt;
        double var  = sumsq_g[c] / cnt - mean * mean;
        float rstd  = (float)(1.0 / sqrt(var + 1e-5));
        float sc    = gamma[c] * rstd;
        scale[c]    = sc;
        shift[c]    = beta[c] - (float)mean * sc;
    }
}

__global__ void apply_bn_relu6(const float* __restrict__ pre,
                               float* __restrict__ out,
                               const float* __restrict__ scale,
                               const float* __restrict__ shift,
                               int total, int HoWo, int Cout)
{
    int i = blockIdx.x * blockDim.x + threadIdx.x;
    if (i < total) {
        int c = (i / HoWo) % Cout;
        out[i] = act6(pre[i], scale[c], shift[c]);
    }
}

struct Layer { int M, M_pad, K, Cout, HoWo; };

extern "C" void kernel_launch(void* const* d_in, const int* in_sizes, int n_in,
                              void* d_out, int out_size)
{
    (void)in_sizes; (void)n_in; (void)out_size;
    const float* x = (const float*)d_in[0];
    const float* W[6]; const float* G[6]; const float* B[6];
    for (int i = 0; i < 6; i++) {
        W[i] = (const float*)d_in[1 + 3 * i];
        G[i] = (const float*)d_in[2 + 3 * i];
        B[i] = (const float*)d_in[3 + 3 * i];
    }

    float *patch, *bufA, *bufB, *wT, *scl, *shf, *sw;
    double *sum, *sq;
    cudaGetSymbolAddress((void**)&patch, g_patch);
    cudaGetSymbolAddress((void**)&bufA,  g_bufA);
    cudaGetSymbolAddress((void**)&bufB,  g_bufB);
    cudaGetSymbolAddress((void**)&wT,    g_wT);
    cudaGetSymbolAddress((void**)&scl,   g_scale);
    cudaGetSymbolAddress((void**)&shf,   g_shift);
    cudaGetSymbolAddress((void**)&sw,    g_sumW);
    cudaGetSymbolAddress((void**)&sum,   g_sum);
    cudaGetSymbolAddress((void**)&sq,    g_sumsq);

    float  *SC[6], *SH[6];
    double *SU[6], *SQ[6];
    for (int i = 0; i < 6; i++) {
        SC[i] = scl + i * 512; SH[i] = shf + i * 512;
        SU[i] = sum + i * 512; SQ[i] = sq  + i * 512;
    }

    zero_stats_kernel<<<12, 256>>>();

    const Layer L[6] = {
        {23104, 23104, 512,  256, 1444},  // L1: 1x1 512->256 @38x38
        {5776,  5824,  2304, 512, 361},   // L2: 3x3 256->512 s2p1 ->19x19
        {5776,  5824,  512,  128, 361},   // L3: 1x1 512->128 @19x19
        {1600,  1600,  1152, 256, 100},   // L4: 3x3 128->256 s2p1 ->10x10
        {1600,  1600,  256,  128, 100},   // L5: 1x1 256->128 @10x10
        {256,   256,   1152, 256, 16},    // L6: 3x3 128->256 s2p0 ->4x4
    };

    const float* srcs[6] = {x, bufA, bufB, bufA, bufB, bufA};
    float*       dsts[6] = {bufA, bufB, bufA, bufB, bufA, bufB};

    for (int li = 0; li < 6; li++) {
        const Layer& l = L[li];
        // prep: patches (with previous layer's BN+ReLU6 folded in)
        if (li == 0) {
            t1x1_kernel<<<dim3((l.M + 255) / 256, l.K), 256>>>(
                srcs[li], patch, nullptr, nullptr, 0, l.M, l.M_pad, l.HoWo, l.K);
        } else if (li == 2) {
            t1x1_kernel<<<dim3((l.M + 255) / 256, l.K), 256>>>(
                srcs[li], patch, SC[1], SH[1], 1, l.M, l.M_pad, l.HoWo, l.K);
        } else if (li == 4) {
            t1x1_kernel<<<dim3((l.M + 255) / 256, l.K), 256>>>(
                srcs[li], patch, SC[3], SH[3], 1, l.M, l.M_pad, l.HoWo, l.K);
        } else if (li == 1) {
            im2col3x3_kernel<<<dim3((l.M + 255) / 256, l.K), 256>>>(
                srcs[li], patch, SC[0], SH[0], l.M, l.M_pad, 256, 38, 38, 19, 19, 2, 1);
        } else if (li == 3) {
            im2col3x3_kernel<<<dim3((l.M + 255) / 256, l.K), 256>>>(
                srcs[li], patch, SC[2], SH[2], l.M, l.M_pad, 128, 19, 19, 10, 10, 2, 1);
        } else {
            im2col3x3_kernel<<<dim3((l.M + 255) / 256, l.K), 256>>>(
                srcs[li], patch, SC[4], SH[4], l.M, l.M_pad, 128, 10, 10, 4, 4, 2, 0);
        }
        // col sums + transposed weights
        sumW_kernel<<<l.Cout, 32>>>(W[li], sw, l.K);
        wtrans_kernel<<<dim3(l.K / 32, l.Cout / 32), dim3(32, 8)>>>(W[li], wT, l.K, l.Cout);
        // GEMM + fused Sp + fused stats
        adder_gemm<<<dim3(l.M_pad / 64, l.Cout / 32), 128>>>(
            patch, wT, sw, dsts[li], SU[li], SQ[li], l.M, l.M_pad, l.K, l.Cout, l.HoWo);
        finalize_bn<<<(l.Cout + 127) / 128, 128>>>(SU[li], SQ[li], G[li], B[li],
                                                   SC[li], SH[li], l.Cout, l.M);
    }

    // Final BN + ReLU6 -> d_out  [16, 256, 4, 4]
    int total = 16 * 256 * 4 * 4;
    apply_bn_relu6<<<(total + 255) / 256, 256>>>(bufB, (float*)d_out, SC[5], SH[5],
                                                 total, 16, 256);
}

// round 11
// speedup vs baseline: 3.0024x; 1.0989x over previous
#include <cuda_runtime.h>

typedef unsigned long long u64;

// acc += 2.0 * {lo, hi}  (packed f32x2 FMA on the fma pipe)
__device__ __forceinline__ void fma2acc(u64& acc, float lo, float hi) {
    asm("{\n\t.reg .b64 t;\n\tmov.b64 t, {%1, %2};\n\tfma.rn.f32x2 %0, t, %3, %0;\n\t}"
        : "+l"(acc) : "f"(lo), "f"(hi), "l"(0x4000000040000000ull));
}
// acc += {lo, hi}  (packed f32x2 add on the fma pipe)
__device__ __forceinline__ void add2acc(u64& acc, float lo, float hi) {
    asm("{\n\t.reg .b64 t;\n\tmov.b64 t, {%1, %2};\n\tadd.rn.f32x2 %0, %0, t;\n\t}"
        : "+l"(acc) : "f"(lo), "f"(hi));
}

__device__ __forceinline__ void cp_async16(unsigned smem_addr, const void* gptr) {
    asm volatile("cp.async.cg.shared.global [%0], [%1], 16;" :: "r"(smem_addr), "l"(gptr));
}
__device__ __forceinline__ void cp_commit() {
    asm volatile("cp.async.commit_group;");
}
template<int N>
__device__ __forceinline__ void cp_wait() {
    asm volatile("cp.async.wait_group %0;" :: "n"(N));
}

// ---------------- scratch (device globals; no runtime allocation) ----------
__device__ float  g_patch[13565952];            // [K][M_pad] patches (max 54.3 MB)
__device__ float  g_bufA[16 * 256 * 38 * 38];   // act ping (pre-BN), 23.7 MB
__device__ float  g_bufB[16 * 512 * 19 * 19];   // act pong, 11.8 MB
__device__ float  g_wT[2304 * 512];             // transposed weights [k][Cout]
__device__ float  g_sumW[6][512];               // per-layer Sw[co]
__device__ double g_sum[6][512];
__device__ double g_sumsq[6][512];
__device__ float  g_scale[6][512];
__device__ float  g_shift[6][512];

__global__ void zero_stats_kernel() {
    int i = blockIdx.x * blockDim.x + threadIdx.x;
    if (i < 6 * 512) {
        (&g_sum[0][0])[i]   = 0.0;
        (&g_sumsq[0][0])[i] = 0.0;
        (&g_sumW[0][0])[i]  = 0.f;
    }
}

__device__ __forceinline__ float act6(float v, float sc, float sh) {
    return fminf(fmaxf(fmaf(v, sc, sh), 0.f), 6.f);
}

// ---- 1x1 layers: NCHW -> [k][M_pad] transpose, BN+ReLU6 fold, 4 m/thread --
__global__ void t1x1_kernel(const float* __restrict__ src, float* __restrict__ P,
                            const float* __restrict__ scale,
                            const float* __restrict__ shift, int do_act,
                            int M, int M_pad, int HW, int Cin)
{
    int k  = blockIdx.y;
    int m0 = (blockIdx.x * blockDim.x + threadIdx.x) * 4;
    if (m0 >= M) return;
    float sc = 0.f, sh = 0.f;
    if (do_act) { sc = scale[k]; sh = shift[k]; }
    float4 v;
    float* vp = &v.x;
#pragma unroll
    for (int e = 0; e < 4; e++) {
        int m = m0 + e;                      // M % 4 == 0 -> always in-bounds
        int n = m / HW, s = m - n * HW;
        float x = src[((size_t)n * Cin + k) * HW + s];
        vp[e] = do_act ? act6(x, sc, sh) : x;
    }
    *reinterpret_cast<float4*>(&P[(size_t)k * M_pad + m0]) = v;
}

// ---- 3x3 layers: im2col, BN+ReLU6 fold, OOB->0, 4 m/thread ----------------
__global__ void im2col3x3_kernel(const float* __restrict__ src, float* __restrict__ P,
                                 const float* __restrict__ scale,
                                 const float* __restrict__ shift,
                                 int M, int M_pad, int Cin, int H, int W,
                                 int Ho, int Wo, int stride, int pad)
{
    int k  = blockIdx.y;
    int m0 = (blockIdx.x * blockDim.x + threadIdx.x) * 4;
    if (m0 >= M) return;
    int c  = k / 9;
    int r  = k - 9 * c;
    int ky = r / 3;
    int kx = r - 3 * ky;
    float sc = scale[c], sh = shift[c];
    int HoWo = Ho * Wo;
    float4 v;
    float* vp = &v.x;
#pragma unroll
    for (int e = 0; e < 4; e++) {
        int m  = m0 + e;
        int n  = m / HoWo, s  = m - n * HoWo;
        int oy = s / Wo,   ox = s - oy * Wo;
        int iy = oy * stride - pad + ky;
        int ix = ox * stride - pad + kx;
        float x = 0.f;
        if (iy >= 0 && iy < H && ix >= 0 && ix < W)
            x = act6(src[((size_t)(n * Cin + c) * H + iy) * W + ix], sc, sh);
        vp[e] = x;
    }
    *reinterpret_cast<float4*>(&P[(size_t)k * M_pad + m0]) = v;
}

// ---- weights: transpose to [k][Cout] + fused column sums (atomicAdd) ------
__global__ void wtrans_kernel(const float* __restrict__ w, float* __restrict__ wT,
                              float* __restrict__ Sw, int K, int Cout)
{
    __shared__ float t[32][33];
    int bk  = blockIdx.x * 32;
    int bco = blockIdx.y * 32;
    int tx  = threadIdx.x, ty = threadIdx.y;   // (32, 8)
#pragma unroll
    for (int i = 0; i < 4; i++) {
        int co = bco + ty + i * 8;
        t[ty + i * 8][tx] = w[(size_t)co * K + bk + tx];
    }
    __syncthreads();
#pragma unroll
    for (int i = 0; i < 4; i++) {
        int k = bk + ty + i * 8;
        wT[(size_t)k * Cout + bco + tx] = t[tx][ty + i * 8];
    }
    if (ty == 0) {                              // fused Sw partial sums
        float s = 0.f;
#pragma unroll
        for (int i = 0; i < 32; i++) s += t[tx][i];
        atomicAdd(&Sw[bco + tx], s);
    }
}

// ---------------------------------------------------------------------------
// Adder GEMM via min-identity:
//   pre[m,co] = 2*sum_k min(P[k,m],W[co,k]) - Sp[m] - Sw[co]
// BM=64 BN=64 TM=4 TN=8, BK=32, cp.async double-buffered, Sp fused in-loop.
// Per kk/thread: 32 FMNMX (alu, binding) + 18 f32x2 (fma) + 3 LDS.
// ---------------------------------------------------------------------------
__global__ __launch_bounds__(128, 6)
void adder_gemm(const float* __restrict__ P, const float* __restrict__ Wt,
                const float* __restrict__ Sw,
                float* __restrict__ out,
                double* __restrict__ sum_g, double* __restrict__ sumsq_g,
                int M, int M_pad, int K, int Cout, int HoWo)
{
    constexpr int BK = 32, BM = 64, BN = 64, TN = 8;
    constexpr int NT = 128;
    __shared__ float sP[2][BK][BM];
    __shared__ float sW[2][BK][BN];

    const int tid = threadIdx.x;
    const int m0  = blockIdx.x * BM;
    const int n0  = blockIdx.y * BN;
    const int txm = tid & 15;
    const int ty  = tid >> 4;
    const int tn0 = ty * TN;

    u64 acc[2][TN];
    u64 sp2[2] = {0ull, 0ull};
#pragma unroll
    for (int i = 0; i < 2; i++)
#pragma unroll
        for (int j = 0; j < TN; j++) acc[i][j] = 0ull;

    const float* gP = P  + m0;
    const float* gW = Wt + n0;
    const int nTiles = K / BK;

    auto issue_tile = [&](int t, int buf) {
        const float* bP = gP + (size_t)t * BK * M_pad;
        const float* bW = gW + (size_t)t * BK * Cout;
        // P tile: 512 16B chunks, 4 per thread
#pragma unroll
        for (int r = 0; r < 4; r++) {
            int idx = r * NT + tid;
            int lk  = idx >> 4;
            int c4  = idx & 15;
            cp_async16((unsigned)__cvta_generic_to_shared(&sP[buf][lk][c4 * 4]),
                       bP + (size_t)lk * M_pad + c4 * 4);
        }
        // W tile: 512 16B chunks, 4 per thread
#pragma unroll
        for (int r = 0; r < 4; r++) {
            int idx = r * NT + tid;
            int lk  = idx >> 4;
            int c4  = idx & 15;
            cp_async16((unsigned)__cvta_generic_to_shared(&sW[buf][lk][c4 * 4]),
                       bW + (size_t)lk * Cout + c4 * 4);
        }
        cp_commit();
    };

    issue_tile(0, 0);

    for (int t = 0; t < nTiles; t++) {
        int buf = t & 1;
        if (t + 1 < nTiles) {
            issue_tile(t + 1, buf ^ 1);
            cp_wait<1>();
        } else {
            cp_wait<0>();
        }
        __syncthreads();

#pragma unroll
        for (int kk = 0; kk < BK; kk++) {
            // P: quarter-warp spans 8 consecutive 16B chunks -> conflict-free
            float4 p = *reinterpret_cast<const float4*>(&sP[buf][kk][txm * 4]);
            // W: quarter-warp shares ty -> broadcast
            float4 wa = *reinterpret_cast<const float4*>(&sW[buf][kk][tn0]);
            float4 wb = *reinterpret_cast<const float4*>(&sW[buf][kk][tn0 + 4]);
            float wv[8] = {wa.x, wa.y, wa.z, wa.w, wb.x, wb.y, wb.z, wb.w};
            // in-loop Sp accumulation (fma pipe)
            add2acc(sp2[0], p.x, p.y);
            add2acc(sp2[1], p.z, p.w);
#pragma unroll
            for (int j = 0; j < TN; j++) {
                fma2acc(acc[0][j], fminf(p.x, wv[j]), fminf(p.y, wv[j]));
                fma2acc(acc[1][j], fminf(p.z, wv[j]), fminf(p.w, wv[j]));
            }
        }
        __syncthreads();
    }

    // ---- epilogue: val = acc(=2*sum min) - Sp[m] - Sw[co]; fused BN stats --
    float4 swa = *reinterpret_cast<const float4*>(&Sw[n0 + tn0]);
    float4 swb = *reinterpret_cast<const float4*>(&Sw[n0 + tn0 + 4]);
    float swA[8] = {swa.x, swa.y, swa.z, swa.w, swb.x, swb.y, swb.z, swb.w};
    float spL[4];
    spL[0] = __uint_as_float((unsigned int)(sp2[0] & 0xFFFFFFFFull));
    spL[1] = __uint_as_float((unsigned int)(sp2[0] >> 32));
    spL[2] = __uint_as_float((unsigned int)(sp2[1] & 0xFFFFFFFFull));
    spL[3] = __uint_as_float((unsigned int)(sp2[1] >> 32));

    float s_sum[TN], s_sq[TN];
#pragma unroll
    for (int j = 0; j < TN; j++) { s_sum[j] = 0.f; s_sq[j] = 0.f; }

#pragma unroll
    for (int i = 0; i < 2; i++) {
        int mA = m0 + txm * 4 + 2 * i;
        int mB = mA + 1;
        bool okA = mA < M, okB = mB < M;
        int nA = 0, sA = 0, nB = 0, sB = 0;
        if (okA) { nA = mA / HoWo; sA = mA - nA * HoWo; }
        if (okB) { nB = mB / HoWo; sB = mB - nB * HoWo; }
#pragma unroll
        for (int j = 0; j < TN; j++) {
            float lo = __uint_as_float((unsigned int)(acc[i][j] & 0xFFFFFFFFull));
            float hi = __uint_as_float((unsigned int)(acc[i][j] >> 32));
            float vA = lo - spL[2 * i]     - swA[j];
            float vB = hi - spL[2 * i + 1] - swA[j];
            int c = n0 + tn0 + j;
            if (okA) {
                out[(size_t)(nA * Cout + c) * HoWo + sA] = vA;
                s_sum[j] += vA; s_sq[j] += vA * vA;
            }
            if (okB) {
                out[(size_t)(nB * Cout + c) * HoWo + sB] = vB;
                s_sum[j] += vB; s_sq[j] += vB * vB;
            }
        }
    }
#pragma unroll
    for (int j = 0; j < TN; j++) {
        float a = s_sum[j], b = s_sq[j];
#pragma unroll
        for (int o = 1; o < 16; o <<= 1) {
            a += __shfl_xor_sync(0xffffffffu, a, o);
            b += __shfl_xor_sync(0xffffffffu, b, o);
        }
        if (txm == 0) {
            int c = n0 + tn0 + j;
            atomicAdd(&sum_g[c],   (double)a);
            atomicAdd(&sumsq_g[c], (double)b);
        }
    }
}

__global__ void finalize_bn(const double* __restrict__ sum_g,
                            const double* __restrict__ sumsq_g,
                            const float* __restrict__ gamma,
                            const float* __restrict__ beta,
                            float* __restrict__ scale,
                            float* __restrict__ shift,
                            int Cout, int cnt)
{
    int c = blockIdx.x * blockDim.x + threadIdx.x;
    if (c < Cout) {
        double mean = sum_g[c] / cnt;
        double var  = sumsq_g[c] / cnt - mean * mean;
        float rstd  = (float)(1.0 / sqrt(var + 1e-5));
        float sc    = gamma[c] * rstd;
        scale[c]    = sc;
        shift[c]    = beta[c] - (float)mean * sc;
    }
}

__global__ void apply_bn_relu6(const float* __restrict__ pre,
                               float* __restrict__ out,
                               const float* __restrict__ scale,
                               const float* __restrict__ shift,
                               int total, int HoWo, int Cout)
{
    int i = blockIdx.x * blockDim.x + threadIdx.x;
    if (i < total) {
        int c = (i / HoWo) % Cout;
        out[i] = act6(pre[i], scale[c], shift[c]);
    }
}

struct Layer { int M, M_pad, K, Cout, HoWo; };

extern "C" void kernel_launch(void* const* d_in, const int* in_sizes, int n_in,
                              void* d_out, int out_size)
{
    (void)in_sizes; (void)n_in; (void)out_size;
    const float* x = (const float*)d_in[0];
    const float* W[6]; const float* G[6]; const float* B[6];
    for (int i = 0; i < 6; i++) {
        W[i] = (const float*)d_in[1 + 3 * i];
        G[i] = (const float*)d_in[2 + 3 * i];
        B[i] = (const float*)d_in[3 + 3 * i];
    }

    float *patch, *bufA, *bufB, *wT, *scl, *shf, *sw;
    double *sum, *sq;
    cudaGetSymbolAddress((void**)&patch, g_patch);
    cudaGetSymbolAddress((void**)&bufA,  g_bufA);
    cudaGetSymbolAddress((void**)&bufB,  g_bufB);
    cudaGetSymbolAddress((void**)&wT,    g_wT);
    cudaGetSymbolAddress((void**)&scl,   g_scale);
    cudaGetSymbolAddress((void**)&shf,   g_shift);
    cudaGetSymbolAddress((void**)&sw,    g_sumW);
    cudaGetSymbolAddress((void**)&sum,   g_sum);
    cudaGetSymbolAddress((void**)&sq,    g_sumsq);

    float  *SC[6], *SH[6], *SW6[6];
    double *SU[6], *SQ[6];
    for (int i = 0; i < 6; i++) {
        SC[i] = scl + i * 512; SH[i] = shf + i * 512; SW6[i] = sw + i * 512;
        SU[i] = sum + i * 512; SQ[i] = sq  + i * 512;
    }

    zero_stats_kernel<<<12, 256>>>();

    const Layer L[6] = {
        {23104, 23104, 512,  256, 1444},  // L1: 1x1 512->256 @38x38
        {5776,  5824,  2304, 512, 361},   // L2: 3x3 256->512 s2p1 ->19x19
        {5776,  5824,  512,  128, 361},   // L3: 1x1 512->128 @19x19
        {1600,  1600,  1152, 256, 100},   // L4: 3x3 128->256 s2p1 ->10x10
        {1600,  1600,  256,  128, 100},   // L5: 1x1 256->128 @10x10
        {256,   256,   1152, 256, 16},    // L6: 3x3 128->256 s2p0 ->4x4
    };

    const float* srcs[6] = {x, bufA, bufB, bufA, bufB, bufA};
    float*       dsts[6] = {bufA, bufB, bufA, bufB, bufA, bufB};

    for (int li = 0; li < 6; li++) {
        const Layer& l = L[li];
        int mth = l.M / 4;                       // all M divisible by 4
        // prep: patches (with previous layer's BN+ReLU6 folded in)
        if (li == 0) {
            t1x1_kernel<<<dim3((mth + 255) / 256, l.K), 256>>>(
                srcs[li], patch, nullptr, nullptr, 0, l.M, l.M_pad, l.HoWo, l.K);
        } else if (li == 2) {
            t1x1_kernel<<<dim3((mth + 255) / 256, l.K), 256>>>(
                srcs[li], patch, SC[1], SH[1], 1, l.M, l.M_pad, l.HoWo, l.K);
        } else if (li == 4) {
            t1x1_kernel<<<dim3((mth + 255) / 256, l.K), 256>>>(
                srcs[li], patch, SC[3], SH[3], 1, l.M, l.M_pad, l.HoWo, l.K);
        } else if (li == 1) {
            im2col3x3_kernel<<<dim3((mth + 255) / 256, l.K), 256>>>(
                srcs[li], patch, SC[0], SH[0], l.M, l.M_pad, 256, 38, 38, 19, 19, 2, 1);
        } else if (li == 3) {
            im2col3x3_kernel<<<dim3((mth + 255) / 256, l.K), 256>>>(
                srcs[li], patch, SC[2], SH[2], l.M, l.M_pad, 128, 19, 19, 10, 10, 2, 1);
        } else {
            im2col3x3_kernel<<<dim3((mth + 255) / 256, l.K), 256>>>(
                srcs[li], patch, SC[4], SH[4], l.M, l.M_pad, 128, 10, 10, 4, 4, 2, 0);
        }
        // transposed weights + fused column sums
        wtrans_kernel<<<dim3(l.K / 32, l.Cout / 32), dim3(32, 8)>>>(
            W[li], wT, SW6[li], l.K, l.Cout);
        // GEMM + fused Sp + fused stats
        adder_gemm<<<dim3(l.M_pad / 64, l.Cout / 64), 128>>>(
            patch, wT, SW6[li], dsts[li], SU[li], SQ[li],
            l.M, l.M_pad, l.K, l.Cout, l.HoWo);
        finalize_bn<<<(l.Cout + 127) / 128, 128>>>(SU[li], SQ[li], G[li], B[li],
                                                   SC[li], SH[li], l.Cout, l.M);
    }

    // Final BN + ReLU6 -> d_out  [16, 256, 4, 4]
    int total = 16 * 256 * 4 * 4;
    apply_bn_relu6<<<(total + 255) / 256, 256>>>(bufB, (float*)d_out, SC[5], SH[5],
                                                 total, 16, 256);
}

// round 12
// speedup vs baseline: 3.0562x; 1.0179x over previous
#include <cuda_runtime.h>

typedef unsigned long long u64;

// acc += 2.0 * {lo, hi}  (packed f32x2 FMA on the fma pipe)
__device__ __forceinline__ void fma2acc(u64& acc, float lo, float hi) {
    asm("{\n\t.reg .b64 t;\n\tmov.b64 t, {%1, %2};\n\tfma.rn.f32x2 %0, t, %3, %0;\n\t}"
        : "+l"(acc) : "f"(lo), "f"(hi), "l"(0x4000000040000000ull));
}
// acc += {lo, hi}  (packed f32x2 add on the fma pipe)
__device__ __forceinline__ void add2acc(u64& acc, float lo, float hi) {
    asm("{\n\t.reg .b64 t;\n\tmov.b64 t, {%1, %2};\n\tadd.rn.f32x2 %0, %0, t;\n\t}"
        : "+l"(acc) : "f"(lo), "f"(hi));
}

__device__ __forceinline__ void cp_async16(unsigned smem_addr, const void* gptr) {
    asm volatile("cp.async.cg.shared.global [%0], [%1], 16;" :: "r"(smem_addr), "l"(gptr));
}
__device__ __forceinline__ void cp_commit() {
    asm volatile("cp.async.commit_group;");
}
template<int N>
__device__ __forceinline__ void cp_wait() {
    asm volatile("cp.async.wait_group %0;" :: "n"(N));
}

// ---------------- scratch (device globals; no runtime allocation) ----------
__device__ float  g_patch[13565952];            // [K][M_pad] patches (3x3 layers)
__device__ float  g_bufA[16 * 256 * 38 * 38];   // act ping (pre-BN), 23.7 MB
__device__ float  g_bufB[16 * 512 * 19 * 19];   // act pong, 11.8 MB
__device__ float  g_wT[2304 * 512];             // transposed weights [k][Cout]
__device__ float  g_sumW[6][512];               // per-layer Sw[co]
__device__ double g_sum[6][512];
__device__ double g_sumsq[6][512];
__device__ float  g_scale[6][512];
__device__ float  g_shift[6][512];

__global__ void zero_stats_kernel() {
    int i = blockIdx.x * blockDim.x + threadIdx.x;
    if (i < 6 * 512) {
        (&g_sum[0][0])[i]   = 0.0;
        (&g_sumsq[0][0])[i] = 0.0;
        (&g_sumW[0][0])[i]  = 0.f;
    }
}

__device__ __forceinline__ float act6(float v, float sc, float sh) {
    return fminf(fmaxf(fmaf(v, sc, sh), 0.f), 6.f);
}

// ---- 1x1 layers (L3/L5): NCHW -> [k][M_pad] transpose with BN fold --------
__global__ void t1x1_kernel(const float* __restrict__ src, float* __restrict__ P,
                            const float* __restrict__ scale,
                            const float* __restrict__ shift,
                            int M, int M_pad, int HW, int Cin)
{
    int k  = blockIdx.y;
    int m0 = (blockIdx.x * blockDim.x + threadIdx.x) * 4;
    if (m0 >= M) return;
    float sc = scale[k], sh = shift[k];
    float4 v;
    float* vp = &v.x;
#pragma unroll
    for (int e = 0; e < 4; e++) {
        int m = m0 + e;
        int n = m / HW, s = m - n * HW;
        vp[e] = act6(src[((size_t)n * Cin + k) * HW + s], sc, sh);
    }
    *reinterpret_cast<float4*>(&P[(size_t)k * M_pad + m0]) = v;
}

// ---- 3x3 layers: im2col, BN+ReLU6 fold, OOB->0, 4 m/thread ----------------
__global__ void im2col3x3_kernel(const float* __restrict__ src, float* __restrict__ P,
                                 const float* __restrict__ scale,
                                 const float* __restrict__ shift,
                                 int M, int M_pad, int Cin, int H, int W,
                                 int Ho, int Wo, int stride, int pad)
{
    int k  = blockIdx.y;
    int m0 = (blockIdx.x * blockDim.x + threadIdx.x) * 4;
    if (m0 >= M) return;
    int c  = k / 9;
    int r  = k - 9 * c;
    int ky = r / 3;
    int kx = r - 3 * ky;
    float sc = scale[c], sh = shift[c];
    int HoWo = Ho * Wo;
    float4 v;
    float* vp = &v.x;
#pragma unroll
    for (int e = 0; e < 4; e++) {
        int m  = m0 + e;
        int n  = m / HoWo, s  = m - n * HoWo;
        int oy = s / Wo,   ox = s - oy * Wo;
        int iy = oy * stride - pad + ky;
        int ix = ox * stride - pad + kx;
        float x = 0.f;
        if (iy >= 0 && iy < H && ix >= 0 && ix < W)
            x = act6(src[((size_t)(n * Cin + c) * H + iy) * W + ix], sc, sh);
        vp[e] = x;
    }
    *reinterpret_cast<float4*>(&P[(size_t)k * M_pad + m0]) = v;
}

// ---- weights: transpose to [k][Cout] + fused column sums ------------------
__global__ void wtrans_kernel(const float* __restrict__ w, float* __restrict__ wT,
                              float* __restrict__ Sw, int K, int Cout)
{
    __shared__ float t[32][33];
    int bk  = blockIdx.x * 32;
    int bco = blockIdx.y * 32;
    int tx  = threadIdx.x, ty = threadIdx.y;   // (32, 8)
#pragma unroll
    for (int i = 0; i < 4; i++) {
        int co = bco + ty + i * 8;
        t[ty + i * 8][tx] = w[(size_t)co * K + bk + tx];
    }
    __syncthreads();
#pragma unroll
    for (int i = 0; i < 4; i++) {
        int k = bk + ty + i * 8;
        wT[(size_t)k * Cout + bco + tx] = t[tx][ty + i * 8];
    }
    if (ty == 0) {
        float s = 0.f;
#pragma unroll
        for (int i = 0; i < 32; i++) s += t[tx][i];
        atomicAdd(&Sw[bco + tx], s);
    }
}

// ---------------------------------------------------------------------------
// Adder GEMM via min-identity:
//   pre[m,co] = 2*sum_k min(P[k,m],W[co,k]) - Sp[m] - Sw[co]
// DIRECT=0: P from pre-built patch [K][M_pad].
// DIRECT=1: P cp.async'd straight from NCHW source (per-image padded m;
//           tiles never straddle images; s clamped for pad lanes).
// BM=64 BN=64 TN=8, BK=32, cp.async double-buffered, Sp fused in-loop.
// ---------------------------------------------------------------------------
template<int DIRECT>
__global__ __launch_bounds__(128, 5)
void adder_gemm(const float* __restrict__ P, const float* __restrict__ Wt,
                const float* __restrict__ Sw,
                float* __restrict__ out,
                double* __restrict__ sum_g, double* __restrict__ sumsq_g,
                int M, int M_pad, int K, int Cout, int HoWo,
                int HWpad, int clamp_s)
{
    constexpr int BK = 32, BM = 64, BN = 64, TN = 8;
    constexpr int NT = 128;
    __shared__ float sP[2][BK][BM];
    __shared__ float sW[2][BK][BN];

    const int tid = threadIdx.x;
    const int m0  = blockIdx.x * BM;
    const int n0  = blockIdx.y * BN;
    const int txm = tid & 15;
    const int ty  = tid >> 4;
    const int tn0 = ty * TN;

    // DIRECT: block's image + spatial base (tile within one image)
    const int n_img = DIRECT ? (m0 / HWpad) : 0;
    const int s0    = DIRECT ? (m0 - n_img * HWpad) : 0;

    u64 acc[2][TN];
    u64 sp2[2] = {0ull, 0ull};
#pragma unroll
    for (int i = 0; i < 2; i++)
#pragma unroll
        for (int j = 0; j < TN; j++) acc[i][j] = 0ull;

    const float* gP = DIRECT ? (P + ((size_t)n_img * K) * HoWo)   // + k*HoWo + s
                             : (P + m0);
    const float* gW = Wt + n0;
    const int nTiles = K / BK;

    auto issue_tile = [&](int t, int buf) {
        const float* bW = gW + (size_t)t * BK * Cout;
        if (DIRECT) {
            const float* bP = gP + (size_t)t * BK * HoWo;
#pragma unroll
            for (int r = 0; r < 4; r++) {
                int idx = r * NT + tid;
                int lk  = idx >> 4;
                int c4  = idx & 15;
                int s   = s0 + c4 * 4;
                if (s > clamp_s) s = clamp_s;      // pad lanes: clamped (guarded later)
                cp_async16((unsigned)__cvta_generic_to_shared(&sP[buf][lk][c4 * 4]),
                           bP + (size_t)lk * HoWo + s);
            }
        } else {
            const float* bP = gP + (size_t)t * BK * M_pad;
#pragma unroll
            for (int r = 0; r < 4; r++) {
                int idx = r * NT + tid;
                int lk  = idx >> 4;
                int c4  = idx & 15;
                cp_async16((unsigned)__cvta_generic_to_shared(&sP[buf][lk][c4 * 4]),
                           bP + (size_t)lk * M_pad + c4 * 4);
            }
        }
#pragma unroll
        for (int r = 0; r < 4; r++) {
            int idx = r * NT + tid;
            int lk  = idx >> 4;
            int c4  = idx & 15;
            cp_async16((unsigned)__cvta_generic_to_shared(&sW[buf][lk][c4 * 4]),
                       bW + (size_t)lk * Cout + c4 * 4);
        }
        cp_commit();
    };

    issue_tile(0, 0);

    for (int t = 0; t < nTiles; t++) {
        int buf = t & 1;
        if (t + 1 < nTiles) {
            issue_tile(t + 1, buf ^ 1);
            cp_wait<1>();
        } else {
            cp_wait<0>();
        }
        __syncthreads();

#pragma unroll
        for (int kk = 0; kk < BK; kk++) {
            float4 p = *reinterpret_cast<const float4*>(&sP[buf][kk][txm * 4]);
            float4 wa = *reinterpret_cast<const float4*>(&sW[buf][kk][tn0]);
            float4 wb = *reinterpret_cast<const float4*>(&sW[buf][kk][tn0 + 4]);
            float wv[8] = {wa.x, wa.y, wa.z, wa.w, wb.x, wb.y, wb.z, wb.w};
            add2acc(sp2[0], p.x, p.y);
            add2acc(sp2[1], p.z, p.w);
#pragma unroll
            for (int j = 0; j < TN; j++) {
                fma2acc(acc[0][j], fminf(p.x, wv[j]), fminf(p.y, wv[j]));
                fma2acc(acc[1][j], fminf(p.z, wv[j]), fminf(p.w, wv[j]));
            }
        }
        __syncthreads();
    }

    // ---- epilogue: val = acc(=2*sum min) - Sp[m] - Sw[co]; fused BN stats --
    float4 swa = *reinterpret_cast<const float4*>(&Sw[n0 + tn0]);
    float4 swb = *reinterpret_cast<const float4*>(&Sw[n0 + tn0 + 4]);
    float swA[8] = {swa.x, swa.y, swa.z, swa.w, swb.x, swb.y, swb.z, swb.w};
    float spL[4];
    spL[0] = __uint_as_float((unsigned int)(sp2[0] & 0xFFFFFFFFull));
    spL[1] = __uint_as_float((unsigned int)(sp2[0] >> 32));
    spL[2] = __uint_as_float((unsigned int)(sp2[1] & 0xFFFFFFFFull));
    spL[3] = __uint_as_float((unsigned int)(sp2[1] >> 32));

    float s_sum[TN], s_sq[TN];
#pragma unroll
    for (int j = 0; j < TN; j++) { s_sum[j] = 0.f; s_sq[j] = 0.f; }

#pragma unroll
    for (int i = 0; i < 2; i++) {
        bool okA, okB;
        int nA, sA, nB, sB;
        if (DIRECT) {
            sA = s0 + txm * 4 + 2 * i;
            sB = sA + 1;
            nA = nB = n_img;
            okA = sA < HoWo;
            okB = sB < HoWo;
        } else {
            int mA = m0 + txm * 4 + 2 * i;
            int mB = mA + 1;
            okA = mA < M; okB = mB < M;
            nA = okA ? mA / HoWo : 0; sA = mA - nA * HoWo;
            nB = okB ? mB / HoWo : 0; sB = mB - nB * HoWo;
        }
#pragma unroll
        for (int j = 0; j < TN; j++) {
            float lo = __uint_as_float((unsigned int)(acc[i][j] & 0xFFFFFFFFull));
            float hi = __uint_as_float((unsigned int)(acc[i][j] >> 32));
            float vA = lo - spL[2 * i]     - swA[j];
            float vB = hi - spL[2 * i + 1] - swA[j];
            int c = n0 + tn0 + j;
            if (okA) {
                out[(size_t)(nA * Cout + c) * HoWo + sA] = vA;
                s_sum[j] += vA; s_sq[j] += vA * vA;
            }
            if (okB) {
                out[(size_t)(nB * Cout + c) * HoWo + sB] = vB;
                s_sum[j] += vB; s_sq[j] += vB * vB;
            }
        }
    }
#pragma unroll
    for (int j = 0; j < TN; j++) {
        float a = s_sum[j], b = s_sq[j];
#pragma unroll
        for (int o = 1; o < 16; o <<= 1) {
            a += __shfl_xor_sync(0xffffffffu, a, o);
            b += __shfl_xor_sync(0xffffffffu, b, o);
        }
        if (txm == 0) {
            int c = n0 + tn0 + j;
            atomicAdd(&sum_g[c],   (double)a);
            atomicAdd(&sumsq_g[c], (double)b);
        }
    }
}

__global__ void finalize_bn(const double* __restrict__ sum_g,
                            const double* __restrict__ sumsq_g,
                            const float* __restrict__ gamma,
                            const float* __restrict__ beta,
                            float* __restrict__ scale,
                            float* __restrict__ shift,
                            int Cout, int cnt)
{
    int c = blockIdx.x * blockDim.x + threadIdx.x;
    if (c < Cout) {
        double mean = sum_g[c] / cnt;
        double var  = sumsq_g[c] / cnt - mean * mean;
        float rstd  = (float)(1.0 / sqrt(var + 1e-5));
        float sc    = gamma[c] * rstd;
        scale[c]    = sc;
        shift[c]    = beta[c] - (float)mean * sc;
    }
}

__global__ void apply_bn_relu6(const float* __restrict__ pre,
                               float* __restrict__ out,
                               const float* __restrict__ scale,
                               const float* __restrict__ shift,
                               int total, int HoWo, int Cout)
{
    int i = blockIdx.x * blockDim.x + threadIdx.x;
    if (i < total) {
        int c = (i / HoWo) % Cout;
        out[i] = act6(pre[i], scale[c], shift[c]);
    }
}

struct Layer { int M, M_pad, K, Cout, HoWo; };

extern "C" void kernel_launch(void* const* d_in, const int* in_sizes, int n_in,
                              void* d_out, int out_size)
{
    (void)in_sizes; (void)n_in; (void)out_size;
    const float* x = (const float*)d_in[0];
    const float* W[6]; const float* G[6]; const float* B[6];
    for (int i = 0; i < 6; i++) {
        W[i] = (const float*)d_in[1 + 3 * i];
        G[i] = (const float*)d_in[2 + 3 * i];
        B[i] = (const float*)d_in[3 + 3 * i];
    }

    float *patch, *bufA, *bufB, *wT, *scl, *shf, *sw;
    double *sum, *sq;
    cudaGetSymbolAddress((void**)&patch, g_patch);
    cudaGetSymbolAddress((void**)&bufA,  g_bufA);
    cudaGetSymbolAddress((void**)&bufB,  g_bufB);
    cudaGetSymbolAddress((void**)&wT,    g_wT);
    cudaGetSymbolAddress((void**)&scl,   g_scale);
    cudaGetSymbolAddress((void**)&shf,   g_shift);
    cudaGetSymbolAddress((void**)&sw,    g_sumW);
    cudaGetSymbolAddress((void**)&sum,   g_sum);
    cudaGetSymbolAddress((void**)&sq,    g_sumsq);

    float  *SC[6], *SH[6], *SW6[6];
    double *SU[6], *SQ[6];
    for (int i = 0; i < 6; i++) {
        SC[i] = scl + i * 512; SH[i] = shf + i * 512; SW6[i] = sw + i * 512;
        SU[i] = sum + i * 512; SQ[i] = sq  + i * 512;
    }

    zero_stats_kernel<<<12, 256>>>();

    const size_t PAD = 8 * 1024;   // dummy dynamic smem -> 5 blocks/SM

    // ---------------- L1: 1x1 512->256 @38x38, DIRECT from x ----------------
    {
        const int K = 512, Cout = 256, HW = 1444, HWpad = 1472, Nimg = 16;
        const int M = Nimg * HW;               // 23104 (stats count)
        wtrans_kernel<<<dim3(K / 32, Cout / 32), dim3(32, 8)>>>(W[0], wT, SW6[0], K, Cout);
        adder_gemm<1><<<dim3(Nimg * HWpad / 64, Cout / 64), 128, PAD>>>(
            x, wT, SW6[0], bufA, SU[0], SQ[0], M, 0, K, Cout, HW, HWpad, 1440);
        finalize_bn<<<2, 128>>>(SU[0], SQ[0], G[0], B[0], SC[0], SH[0], Cout, M);
    }
    // ---------------- L2: 3x3 256->512 s2p1 -> 19x19 ------------------------
    {
        const int M = 5776, M_pad = 5824, K = 2304, Cout = 512, HoWo = 361;
        im2col3x3_kernel<<<dim3((M / 4 + 255) / 256, K), 256>>>(
            bufA, patch, SC[0], SH[0], M, M_pad, 256, 38, 38, 19, 19, 2, 1);
        wtrans_kernel<<<dim3(K / 32, Cout / 32), dim3(32, 8)>>>(W[1], wT, SW6[1], K, Cout);
        adder_gemm<0><<<dim3(M_pad / 64, Cout / 64), 128, PAD>>>(
            patch, wT, SW6[1], bufB, SU[1], SQ[1], M, M_pad, K, Cout, HoWo, 0, 0);
        finalize_bn<<<4, 128>>>(SU[1], SQ[1], G[1], B[1], SC[1], SH[1], Cout, M);
    }
    // ---------------- L3: 1x1 512->128 @19x19 -------------------------------
    {
        const int M = 5776, M_pad = 5824, K = 512, Cout = 128, HoWo = 361;
        t1x1_kernel<<<dim3((M / 4 + 255) / 256, K), 256>>>(
            bufB, patch, SC[1], SH[1], M, M_pad, HoWo, K);
        wtrans_kernel<<<dim3(K / 32, Cout / 32), dim3(32, 8)>>>(W[2], wT, SW6[2], K, Cout);
        adder_gemm<0><<<dim3(M_pad / 64, Cout / 64), 128, PAD>>>(
            patch, wT, SW6[2], bufA, SU[2], SQ[2], M, M_pad, K, Cout, HoWo, 0, 0);
        finalize_bn<<<1, 128>>>(SU[2], SQ[2], G[2], B[2], SC[2], SH[2], Cout, M);
    }
    // ---------------- L4: 3x3 128->256 s2p1 -> 10x10 ------------------------
    {
        const int M = 1600, M_pad = 1600, K = 1152, Cout = 256, HoWo = 100;
        im2col3x3_kernel<<<dim3((M / 4 + 255) / 256, K), 256>>>(
            bufA, patch, SC[2], SH[2], M, M_pad, 128, 19, 19, 10, 10, 2, 1);
        wtrans_kernel<<<dim3(K / 32, Cout / 32), dim3(32, 8)>>>(W[3], wT, SW6[3], K, Cout);
        adder_gemm<0><<<dim3(M_pad / 64, Cout / 64), 128, PAD>>>(
            patch, wT, SW6[3], bufB, SU[3], SQ[3], M, M_pad, K, Cout, HoWo, 0, 0);
        finalize_bn<<<2, 128>>>(SU[3], SQ[3], G[3], B[3], SC[3], SH[3], Cout, M);
    }
    // ---------------- L5: 1x1 256->128 @10x10 -------------------------------
    {
        const int M = 1600, M_pad = 1600, K = 256, Cout = 128, HoWo = 100;
        t1x1_kernel<<<dim3((M / 4 + 255) / 256, K), 256>>>(
            bufB, patch, SC[3], SH[3], M, M_pad, HoWo, K);
        wtrans_kernel<<<dim3(K / 32, Cout / 32), dim3(32, 8)>>>(W[4], wT, SW6[4], K, Cout);
        adder_gemm<0><<<dim3(M_pad / 64, Cout / 64), 128, PAD>>>(
            patch, wT, SW6[4], bufA, SU[4], SQ[4], M, M_pad, K, Cout, HoWo, 0, 0);
        finalize_bn<<<1, 128>>>(SU[4], SQ[4], G[4], B[4], SC[4], SH[4], Cout, M);
    }
    // ---------------- L6: 3x3 128->256 s2p0 -> 4x4 --------------------------
    {
        const int M = 256, M_pad = 256, K = 1152, Cout = 256, HoWo = 16;
        im2col3x3_kernel<<<dim3(1, K), 256>>>(
            bufA, patch, SC[4], SH[4], M, M_pad, 128, 10, 10, 4, 4, 2, 0);
        wtrans_kernel<<<dim3(K / 32, Cout / 32), dim3(32, 8)>>>(W[5], wT, SW6[5], K, Cout);
        adder_gemm<0><<<dim3(M_pad / 64, Cout / 64), 128, PAD>>>(
            patch, wT, SW6[5], bufB, SU[5], SQ[5], M, M_pad, K, Cout, HoWo, 0, 0);
        finalize_bn<<<2, 128>>>(SU[5], SQ[5], G[5], B[5], SC[5], SH[5], Cout, M);
    }

    // Final BN + ReLU6 -> d_out  [16, 256, 4, 4]
    int total = 16 * 256 * 4 * 4;
    apply_bn_relu6<<<(total + 255) / 256, 256>>>(bufB, (float*)d_out, SC[5], SH[5],
                                                 total, 16, 256);
}